// round 12
// baseline (speedup 1.0000x reference)
#include <cuda_runtime.h>
#include <cuda_bf16.h>
#include <math.h>
#include <stdint.h>

// Problem constants
#define NB 4
#define LSEQ 256
#define MMEM 2
#define DDIM 768
#define HNUM 12
#define FFDIM 3072
#define LAYERS 4
#define TTOT 1032
#define KKEYS 258

typedef __nv_bfloat16 bf16;

// -------- scratch (device globals) --------
__device__ float g_x[TTOT * DDIM];
__device__ float g_q[TTOT * DDIM];
__device__ float g_k[TTOT * DDIM];
__device__ float g_v[TTOT * DDIM];
__device__ float g_ctx[TTOT * DDIM];
__device__ float g_p1[TTOT * DDIM];

__device__ bf16 g_xh[TTOT * DDIM];
__device__ bf16 g_xl[TTOT * DDIM];
__device__ bf16 g_hh[TTOT * FFDIM];
__device__ bf16 g_hl[TTOT * FFDIM];

// pre-split weights (bf16 hi/lo, original [K][N] row-major layout)
__device__ bf16 g_Wqh[LAYERS * DDIM * DDIM];
__device__ bf16 g_Wql[LAYERS * DDIM * DDIM];
__device__ bf16 g_Wkh[LAYERS * DDIM * DDIM];
__device__ bf16 g_Wkl[LAYERS * DDIM * DDIM];
__device__ bf16 g_Wvh[LAYERS * DDIM * DDIM];
__device__ bf16 g_Wvl[LAYERS * DDIM * DDIM];
__device__ bf16 g_W1h[LAYERS * DDIM * FFDIM];
__device__ bf16 g_W1l[LAYERS * DDIM * FFDIM];
__device__ bf16 g_W2h[LAYERS * DDIM * FFDIM];
__device__ bf16 g_W2l[LAYERS * DDIM * FFDIM];

__device__ float g_zero_bias[DDIM];   // zero-initialized

// ================= helpers =================
__device__ __forceinline__ uint32_t packbf(bf16 a, bf16 b) {
    __nv_bfloat162 t = __nv_bfloat162(a, b);
    return *reinterpret_cast<uint32_t*>(&t);
}
__device__ __forceinline__ void split1(float v, bf16& h, bf16& l) {
    h = __float2bfloat16(v);
    l = __float2bfloat16(v - __bfloat162float(h));
}
__device__ __forceinline__ void split4(float4 v, uint2& hi, uint2& lo) {
    bf16 h0, l0, h1, l1, h2, l2, h3, l3;
    split1(v.x, h0, l0); split1(v.y, h1, l1);
    split1(v.z, h2, l2); split1(v.w, h3, l3);
    hi.x = packbf(h0, h1); hi.y = packbf(h2, h3);
    lo.x = packbf(l0, l1); lo.y = packbf(l2, l3);
}
__device__ __forceinline__ uint32_t smem_u32(const void* p) {
    uint32_t a;
    asm("{ .reg .u64 t; cvta.to.shared.u64 t, %1; cvt.u32.u64 %0, t; }" : "=r"(a) : "l"(p));
    return a;
}
__device__ __forceinline__ void ldsm_x4(uint32_t* r, uint32_t addr) {
    asm volatile("ldmatrix.sync.aligned.m8n8.x4.shared.b16 {%0,%1,%2,%3}, [%4];\n"
        : "=r"(r[0]), "=r"(r[1]), "=r"(r[2]), "=r"(r[3]) : "r"(addr));
}
__device__ __forceinline__ void ldsm_x4_t(uint32_t* r, uint32_t addr) {
    asm volatile("ldmatrix.sync.aligned.m8n8.x4.trans.shared.b16 {%0,%1,%2,%3}, [%4];\n"
        : "=r"(r[0]), "=r"(r[1]), "=r"(r[2]), "=r"(r[3]) : "r"(addr));
}
__device__ __forceinline__ void mma_bf16(float* c, const uint32_t* a, const uint32_t* b) {
    asm volatile("mma.sync.aligned.m16n8k16.row.col.f32.bf16.bf16.f32 "
        "{%0,%1,%2,%3}, {%4,%5,%6,%7}, {%8,%9}, {%0,%1,%2,%3};\n"
        : "+f"(c[0]), "+f"(c[1]), "+f"(c[2]), "+f"(c[3])
        : "r"(a[0]), "r"(a[1]), "r"(a[2]), "r"(a[3]), "r"(b[0]), "r"(b[1]));
}
__device__ __forceinline__ void cpa16(uint32_t dst, const void* src, int sz) {
    asm volatile("cp.async.cg.shared.global [%0], [%1], 16, %2;\n"
        :: "r"(dst), "l"(src), "r"(sz));
}
__device__ __forceinline__ void cp_commit() {
    asm volatile("cp.async.commit_group;\n");
}
template<int N>
__device__ __forceinline__ void cp_wait() {
    asm volatile("cp.async.wait_group %0;\n" :: "n"(N));
}

// ================= weight split (no transpose; B stays [K][N]) =================
__global__ void convw_kernel(const float4* __restrict__ src,
                             bf16* __restrict__ h, bf16* __restrict__ l, int n4)
{
    int idx = blockIdx.x * blockDim.x + threadIdx.x;
    if (idx >= n4) return;
    float4 v = src[idx];
    uint2 hi, lo;
    split4(v, hi, lo);
    *(uint2*)&h[idx * 4] = hi;
    *(uint2*)&l[idx * 4] = lo;
}

// ================= embedding =================
__global__ void embed_kernel(const int* __restrict__ ids,
                             const float* __restrict__ memory,
                             const float* __restrict__ emb,
                             const float* __restrict__ pos,
                             float* __restrict__ x,
                             bf16* __restrict__ xh, bf16* __restrict__ xl)
{
    int idx = blockIdx.x * blockDim.x + threadIdx.x;
    if (idx >= TTOT * DDIM) return;
    int t = idx / DDIM;
    int d = idx - t * DDIM;
    float val;
    if (t < NB * MMEM) {
        val = memory[idx] + pos[(t & 1) * DDIM + d];
    } else {
        int tt = t - NB * MMEM;
        int tok = ids[tt];
        val = emb[(size_t)tok * DDIM + d] + pos[(MMEM + (tt & (LSEQ - 1))) * DDIM + d];
    }
    x[idx] = val;
    bf16 h, l;
    split1(val, h, l);
    xh[idx] = h; xl[idx] = l;
}

// ================= pipelined bf16x3 GEMM (mma.sync) =================
// BM=128, BN=128, BK=32; 256 threads, 8 warps (2m x 4n), warptile 64x32.
// 3-stage cp.async pipeline. A:[M,K] bf16 hi/lo; B:[K,N] bf16 hi/lo.
// Stage layout (32KB): Ah 8K | Al 8K | Bh 8K | Bl 8K.
// A row = 32 bf16 = 64B = 4 chunks; swizzle chunk ^= (row>>1)&3.
// B row = 128 bf16 = 256B = 16 chunks; swizzle chunk ^= row&15.

#define ST_BYTES 32768
#define OFF_AH2 0
#define OFF_AL2 8192
#define OFF_BH2 16384
#define OFF_BL2 24576
#define GEMM_SMEM (3 * ST_BYTES)

template<int ACT>
__device__ __forceinline__ void gemm_core(
    const bf16* __restrict__ Agh, const bf16* __restrict__ Agl,
    const bf16* __restrict__ Bgh, const bf16* __restrict__ Bgl,
    const float* __restrict__ bias,
    float* __restrict__ C, bf16* __restrict__ Ch, bf16* __restrict__ Cl,
    int Mr, int K, int Nc, int row0, int col0, int kStart, int kLen)
{
    extern __shared__ char sm[];
    uint32_t base = smem_u32(sm);
    int tid = threadIdx.x;
    int lane = tid & 31, wid = tid >> 5;
    int wm = wid & 1, wn = wid >> 1;          // 2m x 4n
    int lrow = lane & 15, lcol8 = (lane >> 4) * 8;

    float acc[4][4][4];
    #pragma unroll
    for (int mf = 0; mf < 4; mf++)
        #pragma unroll
        for (int nf = 0; nf < 4; nf++)
            #pragma unroll
            for (int r = 0; r < 4; r++) acc[mf][nf][r] = 0.f;

    // ---- load mapping ----
    int ar = tid >> 1, ac0 = (tid & 1) * 2;     // A: row 0..127, 2 chunks of 4
    int br = tid >> 3, bc0 = tid & 7;           // B: row 0..31, chunks c, c+8
    int garow = row0 + ar;
    int aok = (garow < Mr) ? 16 : 0;
    int gar = (garow < Mr) ? garow : 0;
    const bf16* pah = Agh + (size_t)gar * K + kStart;
    const bf16* pal = Agl + (size_t)gar * K + kStart;
    const bf16* pbh = Bgh + (size_t)(kStart + br) * Nc + col0;
    const bf16* pbl = Bgl + (size_t)(kStart + br) * Nc + col0;

    int asw = (ar >> 1) & 3;
    int bsw = br & 15;
    uint32_t aD = base + ar * 64;
    uint32_t bD = base + br * 256;
    uint32_t acs0 = (uint32_t)((ac0 ^ asw) * 16);
    uint32_t acs1 = (uint32_t)(((ac0 + 1) ^ asw) * 16);
    uint32_t bcs0 = (uint32_t)((bc0 ^ bsw) * 16);
    uint32_t bcs1 = (uint32_t)(((bc0 + 8) ^ bsw) * 16);

    auto load_stage = [&](int st, int k0) {
        uint32_t so = (uint32_t)st * ST_BYTES;
        const bf16* ah = pah + k0;
        const bf16* al = pal + k0;
        cpa16(aD + so + OFF_AH2 + acs0, ah + ac0 * 8, aok);
        cpa16(aD + so + OFF_AH2 + acs1, ah + ac0 * 8 + 8, aok);
        cpa16(aD + so + OFF_AL2 + acs0, al + ac0 * 8, aok);
        cpa16(aD + so + OFF_AL2 + acs1, al + ac0 * 8 + 8, aok);
        const bf16* bh = pbh + (size_t)k0 * Nc;
        const bf16* bl = pbl + (size_t)k0 * Nc;
        cpa16(bD + so + OFF_BH2 + bcs0, bh + bc0 * 8, 16);
        cpa16(bD + so + OFF_BH2 + bcs1, bh + bc0 * 8 + 64, 16);
        cpa16(bD + so + OFF_BL2 + bcs0, bl + bc0 * 8, 16);
        cpa16(bD + so + OFF_BL2 + bcs1, bl + bc0 * 8 + 64, 16);
        cp_commit();
    };

    int nit = kLen >> 5;         // >= 2 always here (24 or 48)
    load_stage(0, 0);
    load_stage(1, 32);

    for (int it = 0; it < nit; it++) {
        if (it + 1 < nit) cp_wait<1>(); else cp_wait<0>();
        __syncthreads();
        if (it + 2 < nit) load_stage((it + 2) % 3, (it + 2) * 32);

        uint32_t sb = base + (uint32_t)(it % 3) * ST_BYTES;
        #pragma unroll
        for (int ks = 0; ks < 32; ks += 16) {
            uint32_t bhf[4][2], blf[4][2];
            #pragma unroll
            for (int g = 0; g < 2; g++) {
                int rr = ks + lrow;
                int cc = wn * 32 + g * 16 + lcol8;
                uint32_t ba = sb + rr * 256 + (uint32_t)((((cc >> 3) ^ (rr & 15))) * 16);
                uint32_t t[4];
                ldsm_x4_t(t, ba + OFF_BH2);
                bhf[2*g][0] = t[0]; bhf[2*g][1] = t[1];
                bhf[2*g+1][0] = t[2]; bhf[2*g+1][1] = t[3];
                ldsm_x4_t(t, ba + OFF_BL2);
                blf[2*g][0] = t[0]; blf[2*g][1] = t[1];
                blf[2*g+1][0] = t[2]; blf[2*g+1][1] = t[3];
            }
            #pragma unroll
            for (int mf = 0; mf < 4; mf++) {
                int rr = wm * 64 + mf * 16 + lrow;
                int cc = ks + lcol8;
                uint32_t aa = sb + rr * 64 + (uint32_t)((((cc >> 3) ^ ((rr >> 1) & 3))) * 16);
                uint32_t ahf[4], alf[4];
                ldsm_x4(ahf, aa + OFF_AH2);
                ldsm_x4(alf, aa + OFF_AL2);
                #pragma unroll
                for (int nf = 0; nf < 4; nf++) {
                    mma_bf16(acc[mf][nf], ahf, bhf[nf]);
                    mma_bf16(acc[mf][nf], ahf, blf[nf]);
                    mma_bf16(acc[mf][nf], alf, bhf[nf]);
                }
            }
        }
        // stage (it%3) is only overwritten after next top-of-loop __syncthreads
    }

    // ---- epilogue ----
    #pragma unroll
    for (int mf = 0; mf < 4; mf++) {
        int rb = row0 + wm * 64 + mf * 16 + (lane >> 2);
        #pragma unroll
        for (int nf = 0; nf < 4; nf++) {
            int cc = col0 + wn * 32 + nf * 8 + (lane & 3) * 2;
            float bs0 = bias[cc], bs1 = bias[cc + 1];
            #pragma unroll
            for (int half = 0; half < 2; half++) {
                int r = rb + half * 8;
                if (r >= Mr) continue;
                float v0 = acc[mf][nf][half * 2 + 0] + bs0;
                float v1 = acc[mf][nf][half * 2 + 1] + bs1;
                if (ACT == 1) {
                    v0 = 0.5f * v0 * (1.f + erff(v0 * 0.70710678118654752f));
                    v1 = 0.5f * v1 * (1.f + erff(v1 * 0.70710678118654752f));
                    bf16 h0, l0, h1, l1;
                    split1(v0, h0, l0); split1(v1, h1, l1);
                    *(uint32_t*)&Ch[(size_t)r * Nc + cc] = packbf(h0, h1);
                    *(uint32_t*)&Cl[(size_t)r * Nc + cc] = packbf(l0, l1);
                } else {
                    *(float2*)&C[(size_t)r * Nc + cc] = make_float2(v0, v1);
                }
            }
        }
    }
}

__global__ __launch_bounds__(256, 2)
void qkv_gemm_kernel(const bf16* __restrict__ xh, const bf16* __restrict__ xl,
                     const bf16* __restrict__ Wqh, const bf16* __restrict__ Wql,
                     const bf16* __restrict__ Wkh, const bf16* __restrict__ Wkl,
                     const bf16* __restrict__ Wvh, const bf16* __restrict__ Wvl,
                     const float* __restrict__ bq, const float* __restrict__ bk,
                     const float* __restrict__ bv,
                     float* __restrict__ q, float* __restrict__ k, float* __restrict__ v)
{
    const bf16 *Wh, *Wl; const float* b; float* o;
    if (blockIdx.z == 0)      { Wh = Wqh; Wl = Wql; b = bq; o = q; }
    else if (blockIdx.z == 1) { Wh = Wkh; Wl = Wkl; b = bk; o = k; }
    else                      { Wh = Wvh; Wl = Wvl; b = bv; o = v; }
    gemm_core<0>(xh, xl, Wh, Wl, b, o, nullptr, nullptr,
                 TTOT, DDIM, DDIM, blockIdx.y * 128, blockIdx.x * 128, 0, DDIM);
}

__global__ __launch_bounds__(256, 2)
void ff1_gemm_kernel(const bf16* __restrict__ xh, const bf16* __restrict__ xl,
                     const bf16* __restrict__ W1h, const bf16* __restrict__ W1l,
                     const float* __restrict__ b1,
                     bf16* __restrict__ hh, bf16* __restrict__ hl)
{
    gemm_core<1>(xh, xl, W1h, W1l, b1, nullptr, hh, hl,
                 TTOT, DDIM, FFDIM, blockIdx.y * 128, blockIdx.x * 128, 0, DDIM);
}

__global__ __launch_bounds__(256, 2)
void ff2_gemm_kernel(const bf16* __restrict__ hh, const bf16* __restrict__ hl,
                     const bf16* __restrict__ W2h, const bf16* __restrict__ W2l,
                     const float* __restrict__ b2,
                     float* __restrict__ ctx, float* __restrict__ p1)
{
    int z = blockIdx.z;
    const float* b = (z == 0) ? b2 : g_zero_bias;
    float* o = (z == 0) ? ctx : p1;
    gemm_core<0>(hh, hl, W2h, W2l, b, o, nullptr, nullptr,
                 TTOT, FFDIM, DDIM, blockIdx.y * 128, blockIdx.x * 128,
                 z * (FFDIM / 2), FFDIM / 2);
}

// ================= attention: one warp per (token, head) =================
__global__ __launch_bounds__(128)
void attn_kernel(const float* __restrict__ q, const float* __restrict__ k,
                 const float* __restrict__ v, float* __restrict__ ctx)
{
    int t = blockIdx.x;
    int w = threadIdx.x >> 5;
    int lane = threadIdx.x & 31;
    int head = blockIdx.y * 4 + w;

    __shared__ float sc[4][264];
    __shared__ float qs[4][64];

    int b = (t < 8) ? (t >> 1) : ((t - 8) >> 8);
    const float scale = 0.125f;

    size_t qoff = (size_t)t * DDIM + head * 64;
    qs[w][lane]      = q[qoff + lane];
    qs[w][lane + 32] = q[qoff + lane + 32];
    __syncwarp();

    float mx = -1e30f;
    for (int j = lane; j < KKEYS; j += 32) {
        int key = (j < MMEM) ? (2 * b + j) : (8 + b * LSEQ + j - MMEM);
        const float4* kp = (const float4*)(k + (size_t)key * DDIM + head * 64);
        float d = 0.f;
        #pragma unroll
        for (int i = 0; i < 16; i++) {
            float4 kv = kp[i];
            d += kv.x * qs[w][4*i] + kv.y * qs[w][4*i+1]
               + kv.z * qs[w][4*i+2] + kv.w * qs[w][4*i+3];
        }
        d *= scale;
        sc[w][j] = d;
        mx = fmaxf(mx, d);
    }
    #pragma unroll
    for (int o = 16; o > 0; o >>= 1)
        mx = fmaxf(mx, __shfl_xor_sync(0xffffffffu, mx, o));

    float lsum = 0.f;
    for (int j = lane; j < KKEYS; j += 32) {
        float e = __expf(sc[w][j] - mx);
        sc[w][j] = e;
        lsum += e;
    }
    #pragma unroll
    for (int o = 16; o > 0; o >>= 1)
        lsum += __shfl_xor_sync(0xffffffffu, lsum, o);
    float inv = 1.f / lsum;
    __syncwarp();

    float a0 = 0.f, a1 = 0.f;
    for (int j = 0; j < KKEYS; j++) {
        int key = (j < MMEM) ? (2 * b + j) : (8 + b * LSEQ + j - MMEM);
        float p = sc[w][j];
        const float* vp = v + (size_t)key * DDIM + head * 64;
        a0 += p * vp[lane];
        a1 += p * vp[lane + 32];
    }
    ctx[qoff + lane]      = a0 * inv;
    ctx[qoff + lane + 32] = a1 * inv;
}

// ================= residual add + LN (warp per token) =================
__global__ __launch_bounds__(256)
void add_ln_kernel(float* __restrict__ x, const float* __restrict__ r,
                   const float* __restrict__ r2,
                   const float* __restrict__ g, const float* __restrict__ b,
                   bf16* __restrict__ xh, bf16* __restrict__ xl)
{
    int wid = threadIdx.x >> 5;
    int lane = threadIdx.x & 31;
    int t = blockIdx.x * 8 + wid;
    if (t >= TTOT) return;

    const float4* xp = (const float4*)(x + (size_t)t * DDIM);
    const float4* rp = (const float4*)(r + (size_t)t * DDIM);
    const float4* r2p = r2 ? (const float4*)(r2 + (size_t)t * DDIM) : nullptr;
    const float4* gp = (const float4*)g;
    const float4* bp = (const float4*)b;

    float4 v[6];
    float sum = 0.f;
    #pragma unroll
    for (int i = 0; i < 6; i++) {
        int idx = lane + i * 32;
        float4 a = xp[idx], c = rp[idx];
        v[i] = make_float4(a.x + c.x, a.y + c.y, a.z + c.z, a.w + c.w);
        if (r2p) {
            float4 e = r2p[idx];
            v[i].x += e.x; v[i].y += e.y; v[i].z += e.z; v[i].w += e.w;
        }
        sum += v[i].x + v[i].y + v[i].z + v[i].w;
    }
    #pragma unroll
    for (int o = 16; o > 0; o >>= 1) sum += __shfl_xor_sync(0xffffffffu, sum, o);
    float mu = sum * (1.f / DDIM);

    float var = 0.f;
    #pragma unroll
    for (int i = 0; i < 6; i++) {
        float dx = v[i].x - mu, dy = v[i].y - mu, dz = v[i].z - mu, dw = v[i].w - mu;
        var += dx * dx + dy * dy + dz * dz + dw * dw;
    }
    #pragma unroll
    for (int o = 16; o > 0; o >>= 1) var += __shfl_xor_sync(0xffffffffu, var, o);
    float rstd = rsqrtf(var * (1.f / DDIM) + 1e-5f);

    float4* xo = (float4*)(x + (size_t)t * DDIM);
    #pragma unroll
    for (int i = 0; i < 6; i++) {
        int idx = lane + i * 32;
        float4 gg = gp[idx], bb = bp[idx];
        float4 o;
        o.x = (v[i].x - mu) * rstd * gg.x + bb.x;
        o.y = (v[i].y - mu) * rstd * gg.y + bb.y;
        o.z = (v[i].z - mu) * rstd * gg.z + bb.z;
        o.w = (v[i].w - mu) * rstd * gg.w + bb.w;
        xo[idx] = o;
        uint2 hi, lo;
        split4(o, hi, lo);
        *(uint2*)&xh[(size_t)t * DDIM + idx * 4] = hi;
        *(uint2*)&xl[(size_t)t * DDIM + idx * 4] = lo;
    }
}

// ================= output copy =================
__global__ void copy_out_kernel(const float* __restrict__ x, float* __restrict__ out)
{
    int idx = blockIdx.x * blockDim.x + threadIdx.x;
    if (idx < NB * LSEQ * DDIM)
        out[idx] = x[NB * MMEM * DDIM + idx];
}

extern "C" void kernel_launch(void* const* d_in, const int* in_sizes, int n_in,
                              void* d_out, int out_size)
{
    const int*   ids    = (const int*)  d_in[0];
    const float* memory = (const float*)d_in[1];
    const float* emb    = (const float*)d_in[2];
    const float* pos    = (const float*)d_in[3];
    const float* Wq     = (const float*)d_in[4];
    const float* bq     = (const float*)d_in[5];
    const float* Wk     = (const float*)d_in[6];
    const float* bk     = (const float*)d_in[7];
    const float* Wv     = (const float*)d_in[8];
    const float* bv     = (const float*)d_in[9];
    const float* W1     = (const float*)d_in[10];
    const float* b1     = (const float*)d_in[11];
    const float* W2     = (const float*)d_in[12];
    const float* b2     = (const float*)d_in[13];
    const float* g1     = (const float*)d_in[14];
    const float* be1    = (const float*)d_in[15];
    const float* g2     = (const float*)d_in[16];
    const float* be2    = (const float*)d_in[17];
    float* out = (float*)d_out;

    float *x, *q, *k, *v, *ctx, *p1;
    bf16 *xh, *xl, *hh, *hl;
    bf16 *Wqh, *Wql, *Wkh, *Wkl, *Wvh, *Wvl, *W1h, *W1l, *W2h, *W2l;
    cudaGetSymbolAddress((void**)&x,   g_x);
    cudaGetSymbolAddress((void**)&q,   g_q);
    cudaGetSymbolAddress((void**)&k,   g_k);
    cudaGetSymbolAddress((void**)&v,   g_v);
    cudaGetSymbolAddress((void**)&ctx, g_ctx);
    cudaGetSymbolAddress((void**)&p1,  g_p1);
    cudaGetSymbolAddress((void**)&xh,  g_xh);
    cudaGetSymbolAddress((void**)&xl,  g_xl);
    cudaGetSymbolAddress((void**)&hh,  g_hh);
    cudaGetSymbolAddress((void**)&hl,  g_hl);
    cudaGetSymbolAddress((void**)&Wqh, g_Wqh);
    cudaGetSymbolAddress((void**)&Wql, g_Wql);
    cudaGetSymbolAddress((void**)&Wkh, g_Wkh);
    cudaGetSymbolAddress((void**)&Wkl, g_Wkl);
    cudaGetSymbolAddress((void**)&Wvh, g_Wvh);
    cudaGetSymbolAddress((void**)&Wvl, g_Wvl);
    cudaGetSymbolAddress((void**)&W1h, g_W1h);
    cudaGetSymbolAddress((void**)&W1l, g_W1l);
    cudaGetSymbolAddress((void**)&W2h, g_W2h);
    cudaGetSymbolAddress((void**)&W2l, g_W2l);

    cudaFuncSetAttribute(qkv_gemm_kernel, cudaFuncAttributeMaxDynamicSharedMemorySize, GEMM_SMEM);
    cudaFuncSetAttribute(ff1_gemm_kernel, cudaFuncAttributeMaxDynamicSharedMemorySize, GEMM_SMEM);
    cudaFuncSetAttribute(ff2_gemm_kernel, cudaFuncAttributeMaxDynamicSharedMemorySize, GEMM_SMEM);

    int nqkv4 = LAYERS * DDIM * DDIM / 4;
    int nff4  = LAYERS * DDIM * FFDIM / 4;

    // Launch order puts the first qkv GEMM at launch index 5 (ncu -s 5 -c 1).
    embed_kernel<<<(TTOT * DDIM + 255) / 256, 256>>>(ids, memory, emb, pos, x, xh, xl);
    convw_kernel<<<(nqkv4 + 255) / 256, 256>>>((const float4*)Wq, Wqh, Wql, nqkv4);
    convw_kernel<<<(nqkv4 + 255) / 256, 256>>>((const float4*)Wk, Wkh, Wkl, nqkv4);
    convw_kernel<<<(nqkv4 + 255) / 256, 256>>>((const float4*)Wv, Wvh, Wvl, nqkv4);
    convw_kernel<<<(nff4  + 255) / 256, 256>>>((const float4*)W1, W1h, W1l, nff4);

    const int MB = (TTOT + 127) / 128;          // 9
    dim3 grid_qkv(DDIM / 128, MB, 3);           // (6, 9, 3)
    dim3 grid_ff1(FFDIM / 128, MB);             // (24, 9)
    dim3 grid_ff2(DDIM / 128, MB, 2);           // (6, 9, 2) split-K
    int ln_grid = (TTOT + 7) / 8;               // 129

    for (int i = 0; i < LAYERS; i++) {
        size_t od = (size_t)i * DDIM * DDIM;
        size_t of = (size_t)i * DDIM * FFDIM;
        qkv_gemm_kernel<<<grid_qkv, 256, GEMM_SMEM>>>(
            xh, xl,
            Wqh + od, Wql + od, Wkh + od, Wkl + od, Wvh + od, Wvl + od,
            bq + i * DDIM, bk + i * DDIM, bv + i * DDIM,
            q, k, v);

        attn_kernel<<<dim3(TTOT, HNUM / 4), 128>>>(q, k, v, ctx);

        add_ln_kernel<<<ln_grid, 256>>>(x, ctx, nullptr,
                                        g1 + i * DDIM, be1 + i * DDIM, xh, xl);

        ff1_gemm_kernel<<<grid_ff1, 256, GEMM_SMEM>>>(xh, xl, W1h + of, W1l + of,
                                                      b1 + i * FFDIM, hh, hl);
        if (i == 0)
            convw_kernel<<<(nff4 + 255) / 256, 256>>>((const float4*)W2, W2h, W2l, nff4);
        ff2_gemm_kernel<<<grid_ff2, 256, GEMM_SMEM>>>(hh, hl, W2h + of, W2l + of,
                                                      b2 + i * DDIM, ctx, p1);

        add_ln_kernel<<<ln_grid, 256>>>(x, ctx, p1,
                                        g2 + i * DDIM, be2 + i * DDIM, xh, xl);
    }

    copy_out_kernel<<<(NB * LSEQ * DDIM + 255) / 256, 256>>>(x, out);
}

// round 13
// speedup vs baseline: 1.7615x; 1.7615x over previous
#include <cuda_runtime.h>
#include <cuda_bf16.h>
#include <math.h>
#include <stdint.h>

// Problem constants
#define NB 4
#define LSEQ 256
#define MMEM 2
#define DDIM 768
#define HNUM 12
#define FFDIM 3072
#define LAYERS 4
#define TTOT 1032
#define KKEYS 258

typedef __nv_bfloat16 bf16;

// -------- scratch (device globals) --------
__device__ float g_x[TTOT * DDIM];
__device__ float g_q[TTOT * DDIM];
__device__ float g_k[TTOT * DDIM];
__device__ float g_v[TTOT * DDIM];
__device__ float g_ctx[TTOT * DDIM];
__device__ float g_p1[TTOT * DDIM];

__device__ bf16 g_xh[TTOT * DDIM];
__device__ bf16 g_xl[TTOT * DDIM];
__device__ bf16 g_hh[TTOT * FFDIM];
__device__ bf16 g_hl[TTOT * FFDIM];

// pre-split weights (bf16 hi/lo, original [K][N] row-major layout)
__device__ bf16 g_Wqh[LAYERS * DDIM * DDIM];
__device__ bf16 g_Wql[LAYERS * DDIM * DDIM];
__device__ bf16 g_Wkh[LAYERS * DDIM * DDIM];
__device__ bf16 g_Wkl[LAYERS * DDIM * DDIM];
__device__ bf16 g_Wvh[LAYERS * DDIM * DDIM];
__device__ bf16 g_Wvl[LAYERS * DDIM * DDIM];
__device__ bf16 g_W1h[LAYERS * DDIM * FFDIM];
__device__ bf16 g_W1l[LAYERS * DDIM * FFDIM];
__device__ bf16 g_W2h[LAYERS * DDIM * FFDIM];
__device__ bf16 g_W2l[LAYERS * DDIM * FFDIM];

__device__ float g_zero_bias[DDIM];   // zero-initialized

// ================= helpers =================
__device__ __forceinline__ uint32_t packbf(bf16 a, bf16 b) {
    __nv_bfloat162 t = __nv_bfloat162(a, b);
    return *reinterpret_cast<uint32_t*>(&t);
}
__device__ __forceinline__ void split1(float v, bf16& h, bf16& l) {
    h = __float2bfloat16(v);
    l = __float2bfloat16(v - __bfloat162float(h));
}
__device__ __forceinline__ void split4(float4 v, uint2& hi, uint2& lo) {
    bf16 h0, l0, h1, l1, h2, l2, h3, l3;
    split1(v.x, h0, l0); split1(v.y, h1, l1);
    split1(v.z, h2, l2); split1(v.w, h3, l3);
    hi.x = packbf(h0, h1); hi.y = packbf(h2, h3);
    lo.x = packbf(l0, l1); lo.y = packbf(l2, l3);
}
__device__ __forceinline__ void ldsm_x4(uint32_t* r, uint32_t addr) {
    asm volatile("ldmatrix.sync.aligned.m8n8.x4.shared.b16 {%0,%1,%2,%3}, [%4];\n"
        : "=r"(r[0]), "=r"(r[1]), "=r"(r[2]), "=r"(r[3]) : "r"(addr));
}
__device__ __forceinline__ void ldsm_x4_t(uint32_t* r, uint32_t addr) {
    asm volatile("ldmatrix.sync.aligned.m8n8.x4.trans.shared.b16 {%0,%1,%2,%3}, [%4];\n"
        : "=r"(r[0]), "=r"(r[1]), "=r"(r[2]), "=r"(r[3]) : "r"(addr));
}
__device__ __forceinline__ void mma_bf16(float* c, const uint32_t* a, const uint32_t* b) {
    asm volatile("mma.sync.aligned.m16n8k16.row.col.f32.bf16.bf16.f32 "
        "{%0,%1,%2,%3}, {%4,%5,%6,%7}, {%8,%9}, {%0,%1,%2,%3};\n"
        : "+f"(c[0]), "+f"(c[1]), "+f"(c[2]), "+f"(c[3])
        : "r"(a[0]), "r"(a[1]), "r"(a[2]), "r"(a[3]), "r"(b[0]), "r"(b[1]));
}
__device__ __forceinline__ void cpa16s(void* dst, const void* src, int sz) {
    uint32_t d = (uint32_t)__cvta_generic_to_shared(dst);
    asm volatile("cp.async.cg.shared.global [%0], [%1], 16, %2;\n"
        :: "r"(d), "l"(src), "r"(sz));
}
__device__ __forceinline__ void cp_commit() {
    asm volatile("cp.async.commit_group;\n");
}
template<int N>
__device__ __forceinline__ void cp_wait() {
    asm volatile("cp.async.wait_group %0;\n" :: "n"(N));
}

// smem XOR swizzles (conflict-free for ldmatrix, 16B-aligned for cp.async)
__device__ __forceinline__ int swzA(int row, int col) {   // 32 cols
    int chunk = (col >> 3) ^ ((row >> 1) & 3);
    return row * 32 + chunk * 8;
}
__device__ __forceinline__ int swzB(int row, int col) {   // 64 cols
    int chunk = (col >> 3) ^ (row & 7);
    return row * 64 + chunk * 8;
}

// ================= weight split =================
__global__ void convw_kernel(const float4* __restrict__ src,
                             bf16* __restrict__ h, bf16* __restrict__ l, int n4)
{
    int idx = blockIdx.x * blockDim.x + threadIdx.x;
    if (idx >= n4) return;
    float4 v = src[idx];
    uint2 hi, lo;
    split4(v, hi, lo);
    *(uint2*)&h[idx * 4] = hi;
    *(uint2*)&l[idx * 4] = lo;
}

// ================= embedding =================
__global__ void embed_kernel(const int* __restrict__ ids,
                             const float* __restrict__ memory,
                             const float* __restrict__ emb,
                             const float* __restrict__ pos,
                             float* __restrict__ x,
                             bf16* __restrict__ xh, bf16* __restrict__ xl)
{
    int idx = blockIdx.x * blockDim.x + threadIdx.x;
    if (idx >= TTOT * DDIM) return;
    int t = idx / DDIM;
    int d = idx - t * DDIM;
    float val;
    if (t < NB * MMEM) {
        val = memory[idx] + pos[(t & 1) * DDIM + d];
    } else {
        int tt = t - NB * MMEM;
        int tok = ids[tt];
        val = emb[(size_t)tok * DDIM + d] + pos[(MMEM + (tt & (LSEQ - 1))) * DDIM + d];
    }
    x[idx] = val;
    bf16 h, l;
    split1(val, h, l);
    xh[idx] = h; xl[idx] = l;
}

// ================= pipelined bf16x3 GEMM (R7 config) =================
// BM=128, BN=64, BK=32; 256 threads = 8 warps (4m x 2n), warptile 32x32.

struct __align__(16) SmemGemm {
    bf16 Ah[2][128 * 32];
    bf16 Al[2][128 * 32];
    bf16 Bh[2][32 * 64];
    bf16 Bl[2][32 * 64];
};

template<int ACT>
__device__ __forceinline__ void gemm_core(
    const bf16* __restrict__ Agh, const bf16* __restrict__ Agl,
    const bf16* __restrict__ Bgh, const bf16* __restrict__ Bgl,
    const float* __restrict__ bias,
    float* __restrict__ C, bf16* __restrict__ Ch, bf16* __restrict__ Cl,
    int Mr, int K, int Nc, int row0, int col0, int kStart, int kLen)
{
    __shared__ SmemGemm s;

    int tid = threadIdx.x;
    int lane = tid & 31;
    int wid = tid >> 5;
    int wm = wid & 3;           // 0..3
    int wn = wid >> 2;          // 0..1
    int lrow = lane & 15;
    int lcol8 = (lane >> 4) * 8;

    float acc[2][4][4];
    #pragma unroll
    for (int im = 0; im < 2; im++)
        #pragma unroll
        for (int in = 0; in < 4; in++)
            #pragma unroll
            for (int r = 0; r < 4; r++) acc[im][in][r] = 0.f;

    int arow = tid >> 2;          // 0..63
    int acol = (tid & 3) * 8;     // 0,8,16,24
    int brow = tid >> 3;          // 0..31
    int bcol = (tid & 7) * 8;     // 0..56

    auto load_stage = [&](int st, int k0) {
        #pragma unroll
        for (int i = 0; i < 2; i++) {
            int row = arow + i * 64;
            int grow = row0 + row;
            int ok = (grow < Mr) ? 16 : 0;
            int gr = (grow < Mr) ? grow : 0;
            const bf16* sh = &Agh[(size_t)gr * K + kStart + k0 + acol];
            const bf16* sl = &Agl[(size_t)gr * K + kStart + k0 + acol];
            cpa16s(&s.Ah[st][swzA(row, acol)], sh, ok);
            cpa16s(&s.Al[st][swzA(row, acol)], sl, ok);
        }
        cpa16s(&s.Bh[st][swzB(brow, bcol)],
               &Bgh[(size_t)(kStart + k0 + brow) * Nc + col0 + bcol], 16);
        cpa16s(&s.Bl[st][swzB(brow, bcol)],
               &Bgl[(size_t)(kStart + k0 + brow) * Nc + col0 + bcol], 16);
        cp_commit();
    };

    int nit = kLen / 32;
    load_stage(0, 0);

    for (int iter = 0; iter < nit; iter++) {
        int st = iter & 1;
        if (iter + 1 < nit) {
            load_stage(st ^ 1, (iter + 1) * 32);
            cp_wait<1>();
        } else {
            cp_wait<0>();
        }
        __syncthreads();

        #pragma unroll
        for (int ks = 0; ks < 32; ks += 16) {
            uint32_t ah[2][4], al[2][4];
            #pragma unroll
            for (int im = 0; im < 2; im++) {
                int mrow = wm * 32 + im * 16 + lrow;
                int mcol = ks + lcol8;
                ldsm_x4(ah[im], (uint32_t)__cvta_generic_to_shared(&s.Ah[st][swzA(mrow, mcol)]));
                ldsm_x4(al[im], (uint32_t)__cvta_generic_to_shared(&s.Al[st][swzA(mrow, mcol)]));
            }
            uint32_t bh[4][2], bl[4][2];
            #pragma unroll
            for (int g = 0; g < 2; g++) {
                int br = ks + lrow;
                int bc = wn * 32 + g * 16 + lcol8;
                uint32_t t[4];
                ldsm_x4_t(t, (uint32_t)__cvta_generic_to_shared(&s.Bh[st][swzB(br, bc)]));
                bh[2*g][0] = t[0]; bh[2*g][1] = t[1]; bh[2*g+1][0] = t[2]; bh[2*g+1][1] = t[3];
                ldsm_x4_t(t, (uint32_t)__cvta_generic_to_shared(&s.Bl[st][swzB(br, bc)]));
                bl[2*g][0] = t[0]; bl[2*g][1] = t[1]; bl[2*g+1][0] = t[2]; bl[2*g+1][1] = t[3];
            }
            #pragma unroll
            for (int im = 0; im < 2; im++)
                #pragma unroll
                for (int in = 0; in < 4; in++) {
                    mma_bf16(acc[im][in], ah[im], bh[in]);
                    mma_bf16(acc[im][in], ah[im], bl[in]);
                    mma_bf16(acc[im][in], al[im], bh[in]);
                }
        }
        __syncthreads();
    }

    #pragma unroll
    for (int im = 0; im < 2; im++) {
        int rbase = row0 + wm * 32 + im * 16 + (lane >> 2);
        #pragma unroll
        for (int in = 0; in < 4; in++) {
            int cc = col0 + wn * 32 + in * 8 + (lane & 3) * 2;
            float bs0 = bias[cc], bs1 = bias[cc + 1];
            #pragma unroll
            for (int half = 0; half < 2; half++) {
                int r = rbase + half * 8;
                if (r >= Mr) continue;
                float v0 = acc[im][in][half * 2 + 0] + bs0;
                float v1 = acc[im][in][half * 2 + 1] + bs1;
                if (ACT == 1) {
                    v0 = 0.5f * v0 * (1.f + erff(v0 * 0.70710678118654752f));
                    v1 = 0.5f * v1 * (1.f + erff(v1 * 0.70710678118654752f));
                    bf16 h0, l0, h1, l1;
                    split1(v0, h0, l0); split1(v1, h1, l1);
                    *(uint32_t*)&Ch[(size_t)r * Nc + cc] = packbf(h0, h1);
                    *(uint32_t*)&Cl[(size_t)r * Nc + cc] = packbf(l0, l1);
                } else {
                    *(float2*)&C[(size_t)r * Nc + cc] = make_float2(v0, v1);
                }
            }
        }
    }
}

__global__ __launch_bounds__(256)
void qkv_gemm_kernel(const bf16* __restrict__ xh, const bf16* __restrict__ xl,
                     const bf16* __restrict__ Wqh, const bf16* __restrict__ Wql,
                     const bf16* __restrict__ Wkh, const bf16* __restrict__ Wkl,
                     const bf16* __restrict__ Wvh, const bf16* __restrict__ Wvl,
                     const float* __restrict__ bq, const float* __restrict__ bk,
                     const float* __restrict__ bv,
                     float* __restrict__ q, float* __restrict__ k, float* __restrict__ v)
{
    const bf16 *Wh, *Wl; const float* b; float* o;
    if (blockIdx.z == 0)      { Wh = Wqh; Wl = Wql; b = bq; o = q; }
    else if (blockIdx.z == 1) { Wh = Wkh; Wl = Wkl; b = bk; o = k; }
    else                      { Wh = Wvh; Wl = Wvl; b = bv; o = v; }
    gemm_core<0>(xh, xl, Wh, Wl, b, o, nullptr, nullptr,
                 TTOT, DDIM, DDIM, blockIdx.y * 128, blockIdx.x * 64, 0, DDIM);
}

__global__ __launch_bounds__(256)
void ff1_gemm_kernel(const bf16* __restrict__ xh, const bf16* __restrict__ xl,
                     const bf16* __restrict__ W1h, const bf16* __restrict__ W1l,
                     const float* __restrict__ b1,
                     bf16* __restrict__ hh, bf16* __restrict__ hl)
{
    gemm_core<1>(xh, xl, W1h, W1l, b1, nullptr, hh, hl,
                 TTOT, DDIM, FFDIM, blockIdx.y * 128, blockIdx.x * 64, 0, DDIM);
}

__global__ __launch_bounds__(256)
void ff2_gemm_kernel(const bf16* __restrict__ hh, const bf16* __restrict__ hl,
                     const bf16* __restrict__ W2h, const bf16* __restrict__ W2l,
                     const float* __restrict__ b2,
                     float* __restrict__ ctx, float* __restrict__ p1)
{
    int z = blockIdx.z;
    const float* b = (z == 0) ? b2 : g_zero_bias;
    float* o = (z == 0) ? ctx : p1;
    gemm_core<0>(hh, hl, W2h, W2l, b, o, nullptr, nullptr,
                 TTOT, FFDIM, DDIM, blockIdx.y * 128, blockIdx.x * 64,
                 z * (FFDIM / 2), FFDIM / 2);
}

// ================= attention: block per (batch, head, qhalf) =================
// K/V tiles staged once in dynamic smem (129 KB); one query per thread;
// single-pass softmax (no max subtraction: scores are O(1) by construction).
#define QG 129
#define ATTN_THREADS 160
#define ATTN_SMEM (2 * KKEYS * 64 * 4)

__global__ __launch_bounds__(ATTN_THREADS)
void attn_kernel(const float* __restrict__ q, const float* __restrict__ k,
                 const float* __restrict__ v, float* __restrict__ ctx)
{
    extern __shared__ float asm_[];
    float* Ks = asm_;
    float* Vs = asm_ + KKEYS * 64;

    int b = blockIdx.x;
    int h = blockIdx.y;
    int zg = blockIdx.z;
    int tid = threadIdx.x;

    // stage K and V (258 rows x 64 floats each), coalesced float4
    for (int i = tid; i < KKEYS * 16; i += ATTN_THREADS) {
        int j = i >> 4, c = i & 15;
        int key = (j < MMEM) ? (2 * b + j) : (8 + b * LSEQ + (j - MMEM));
        size_t off = (size_t)key * DDIM + h * 64 + c * 4;
        ((float4*)Ks)[i] = *(const float4*)&k[off];
        ((float4*)Vs)[i] = *(const float4*)&v[off];
    }
    __syncthreads();

    int qi = zg * QG + tid;
    if (tid < QG && qi < KKEYS) {
        int t = (qi < MMEM) ? (2 * b + qi) : (8 + b * LSEQ + (qi - MMEM));
        size_t qoff = (size_t)t * DDIM + h * 64;

        float4 qr[16];
        #pragma unroll
        for (int i = 0; i < 16; i++) {
            float4 qv = *(const float4*)&q[qoff + i * 4];
            qr[i] = make_float4(qv.x * 0.125f, qv.y * 0.125f, qv.z * 0.125f, qv.w * 0.125f);
        }

        float4 acc[16];
        #pragma unroll
        for (int i = 0; i < 16; i++) acc[i] = make_float4(0.f, 0.f, 0.f, 0.f);
        float l = 0.f;

        for (int j = 0; j < KKEYS; j++) {
            const float4* kr = (const float4*)(Ks + j * 64);
            float s = 0.f;
            #pragma unroll
            for (int i = 0; i < 16; i++) {
                float4 kv = kr[i];
                s += qr[i].x * kv.x + qr[i].y * kv.y + qr[i].z * kv.z + qr[i].w * kv.w;
            }
            float p = __expf(s);
            l += p;
            const float4* vr = (const float4*)(Vs + j * 64);
            #pragma unroll
            for (int i = 0; i < 16; i++) {
                float4 vv = vr[i];
                acc[i].x += p * vv.x; acc[i].y += p * vv.y;
                acc[i].z += p * vv.z; acc[i].w += p * vv.w;
            }
        }

        float inv = 1.f / l;
        #pragma unroll
        for (int i = 0; i < 16; i++) {
            float4 o = make_float4(acc[i].x * inv, acc[i].y * inv,
                                   acc[i].z * inv, acc[i].w * inv);
            *(float4*)&ctx[qoff + i * 4] = o;
        }
    }
}

// ================= residual add + LN (warp per token) =================
__global__ __launch_bounds__(256)
void add_ln_kernel(float* __restrict__ x, const float* __restrict__ r,
                   const float* __restrict__ r2,
                   const float* __restrict__ g, const float* __restrict__ b,
                   bf16* __restrict__ xh, bf16* __restrict__ xl)
{
    int wid = threadIdx.x >> 5;
    int lane = threadIdx.x & 31;
    int t = blockIdx.x * 8 + wid;
    if (t >= TTOT) return;

    const float4* xp = (const float4*)(x + (size_t)t * DDIM);
    const float4* rp = (const float4*)(r + (size_t)t * DDIM);
    const float4* r2p = r2 ? (const float4*)(r2 + (size_t)t * DDIM) : nullptr;
    const float4* gp = (const float4*)g;
    const float4* bp = (const float4*)b;

    float4 v[6];
    float sum = 0.f;
    #pragma unroll
    for (int i = 0; i < 6; i++) {
        int idx = lane + i * 32;
        float4 a = xp[idx], c = rp[idx];
        v[i] = make_float4(a.x + c.x, a.y + c.y, a.z + c.z, a.w + c.w);
        if (r2p) {
            float4 e = r2p[idx];
            v[i].x += e.x; v[i].y += e.y; v[i].z += e.z; v[i].w += e.w;
        }
        sum += v[i].x + v[i].y + v[i].z + v[i].w;
    }
    #pragma unroll
    for (int o = 16; o > 0; o >>= 1) sum += __shfl_xor_sync(0xffffffffu, sum, o);
    float mu = sum * (1.f / DDIM);

    float var = 0.f;
    #pragma unroll
    for (int i = 0; i < 6; i++) {
        float dx = v[i].x - mu, dy = v[i].y - mu, dz = v[i].z - mu, dw = v[i].w - mu;
        var += dx * dx + dy * dy + dz * dz + dw * dw;
    }
    #pragma unroll
    for (int o = 16; o > 0; o >>= 1) var += __shfl_xor_sync(0xffffffffu, var, o);
    float rstd = rsqrtf(var * (1.f / DDIM) + 1e-5f);

    float4* xo = (float4*)(x + (size_t)t * DDIM);
    #pragma unroll
    for (int i = 0; i < 6; i++) {
        int idx = lane + i * 32;
        float4 gg = gp[idx], bb = bp[idx];
        float4 o;
        o.x = (v[i].x - mu) * rstd * gg.x + bb.x;
        o.y = (v[i].y - mu) * rstd * gg.y + bb.y;
        o.z = (v[i].z - mu) * rstd * gg.z + bb.z;
        o.w = (v[i].w - mu) * rstd * gg.w + bb.w;
        xo[idx] = o;
        uint2 hi, lo;
        split4(o, hi, lo);
        *(uint2*)&xh[(size_t)t * DDIM + idx * 4] = hi;
        *(uint2*)&xl[(size_t)t * DDIM + idx * 4] = lo;
    }
}

// ================= output copy =================
__global__ void copy_out_kernel(const float* __restrict__ x, float* __restrict__ out)
{
    int idx = blockIdx.x * blockDim.x + threadIdx.x;
    if (idx < NB * LSEQ * DDIM)
        out[idx] = x[NB * MMEM * DDIM + idx];
}

extern "C" void kernel_launch(void* const* d_in, const int* in_sizes, int n_in,
                              void* d_out, int out_size)
{
    const int*   ids    = (const int*)  d_in[0];
    const float* memory = (const float*)d_in[1];
    const float* emb    = (const float*)d_in[2];
    const float* pos    = (const float*)d_in[3];
    const float* Wq     = (const float*)d_in[4];
    const float* bq     = (const float*)d_in[5];
    const float* Wk     = (const float*)d_in[6];
    const float* bk     = (const float*)d_in[7];
    const float* Wv     = (const float*)d_in[8];
    const float* bv     = (const float*)d_in[9];
    const float* W1     = (const float*)d_in[10];
    const float* b1     = (const float*)d_in[11];
    const float* W2     = (const float*)d_in[12];
    const float* b2     = (const float*)d_in[13];
    const float* g1     = (const float*)d_in[14];
    const float* be1    = (const float*)d_in[15];
    const float* g2     = (const float*)d_in[16];
    const float* be2    = (const float*)d_in[17];
    float* out = (float*)d_out;

    float *x, *q, *k, *v, *ctx, *p1;
    bf16 *xh, *xl, *hh, *hl;
    bf16 *Wqh, *Wql, *Wkh, *Wkl, *Wvh, *Wvl, *W1h, *W1l, *W2h, *W2l;
    cudaGetSymbolAddress((void**)&x,   g_x);
    cudaGetSymbolAddress((void**)&q,   g_q);
    cudaGetSymbolAddress((void**)&k,   g_k);
    cudaGetSymbolAddress((void**)&v,   g_v);
    cudaGetSymbolAddress((void**)&ctx, g_ctx);
    cudaGetSymbolAddress((void**)&p1,  g_p1);
    cudaGetSymbolAddress((void**)&xh,  g_xh);
    cudaGetSymbolAddress((void**)&xl,  g_xl);
    cudaGetSymbolAddress((void**)&hh,  g_hh);
    cudaGetSymbolAddress((void**)&hl,  g_hl);
    cudaGetSymbolAddress((void**)&Wqh, g_Wqh);
    cudaGetSymbolAddress((void**)&Wql, g_Wql);
    cudaGetSymbolAddress((void**)&Wkh, g_Wkh);
    cudaGetSymbolAddress((void**)&Wkl, g_Wkl);
    cudaGetSymbolAddress((void**)&Wvh, g_Wvh);
    cudaGetSymbolAddress((void**)&Wvl, g_Wvl);
    cudaGetSymbolAddress((void**)&W1h, g_W1h);
    cudaGetSymbolAddress((void**)&W1l, g_W1l);
    cudaGetSymbolAddress((void**)&W2h, g_W2h);
    cudaGetSymbolAddress((void**)&W2l, g_W2l);

    cudaFuncSetAttribute(attn_kernel, cudaFuncAttributeMaxDynamicSharedMemorySize, ATTN_SMEM);

    int nqkv4 = LAYERS * DDIM * DDIM / 4;
    int nff4  = LAYERS * DDIM * FFDIM / 4;

    embed_kernel<<<(TTOT * DDIM + 255) / 256, 256>>>(ids, memory, emb, pos, x, xh, xl);
    convw_kernel<<<(nqkv4 + 255) / 256, 256>>>((const float4*)Wq, Wqh, Wql, nqkv4);
    convw_kernel<<<(nqkv4 + 255) / 256, 256>>>((const float4*)Wk, Wkh, Wkl, nqkv4);
    convw_kernel<<<(nqkv4 + 255) / 256, 256>>>((const float4*)Wv, Wvh, Wvl, nqkv4);
    convw_kernel<<<(nff4  + 255) / 256, 256>>>((const float4*)W1, W1h, W1l, nff4);

    const int MB = (TTOT + 127) / 128;          // 9
    dim3 grid_qkv(DDIM / 64, MB, 3);            // (12, 9, 3)
    dim3 grid_ff1(FFDIM / 64, MB);              // (48, 9)
    dim3 grid_ff2(DDIM / 64, MB, 2);            // (12, 9, 2) split-K
    dim3 grid_attn(NB, HNUM, 2);                // (4, 12, 2)
    int ln_grid = (TTOT + 7) / 8;               // 129

    for (int i = 0; i < LAYERS; i++) {
        size_t od = (size_t)i * DDIM * DDIM;
        size_t of = (size_t)i * DDIM * FFDIM;
        qkv_gemm_kernel<<<grid_qkv, 256>>>(
            xh, xl,
            Wqh + od, Wql + od, Wkh + od, Wkl + od, Wvh + od, Wvl + od,
            bq + i * DDIM, bk + i * DDIM, bv + i * DDIM,
            q, k, v);

        attn_kernel<<<grid_attn, ATTN_THREADS, ATTN_SMEM>>>(q, k, v, ctx);

        add_ln_kernel<<<ln_grid, 256>>>(x, ctx, nullptr,
                                        g1 + i * DDIM, be1 + i * DDIM, xh, xl);

        ff1_gemm_kernel<<<grid_ff1, 256>>>(xh, xl, W1h + of, W1l + of,
                                           b1 + i * FFDIM, hh, hl);
        if (i == 0)
            convw_kernel<<<(nff4 + 255) / 256, 256>>>((const float4*)W2, W2h, W2l, nff4);
        ff2_gemm_kernel<<<grid_ff2, 256>>>(hh, hl, W2h + of, W2l + of,
                                           b2 + i * DDIM, ctx, p1);

        add_ln_kernel<<<ln_grid, 256>>>(x, ctx, p1,
                                        g2 + i * DDIM, be2 + i * DDIM, xh, xl);
    }

    copy_out_kernel<<<(NB * LSEQ * DDIM + 255) / 256, 256>>>(x, out);
}

// round 14
// speedup vs baseline: 1.7829x; 1.0122x over previous
#include <cuda_runtime.h>
#include <cuda_bf16.h>
#include <math.h>
#include <stdint.h>

// Problem constants
#define NB 4
#define LSEQ 256
#define MMEM 2
#define DDIM 768
#define HNUM 12
#define FFDIM 3072
#define LAYERS 4
#define TTOT 1032
#define KKEYS 258

typedef __nv_bfloat16 bf16;

// -------- scratch (device globals) --------
__device__ float g_x[TTOT * DDIM];
__device__ float g_q[TTOT * DDIM];
__device__ float g_k[TTOT * DDIM];
__device__ float g_v[TTOT * DDIM];
__device__ float g_ctx[TTOT * DDIM];
__device__ float g_p1[TTOT * DDIM];

__device__ bf16 g_xh[TTOT * DDIM];
__device__ bf16 g_xl[TTOT * DDIM];
__device__ bf16 g_hh[TTOT * FFDIM];
__device__ bf16 g_hl[TTOT * FFDIM];

// pre-split weights (bf16 hi/lo, original [K][N] row-major layout)
__device__ bf16 g_Wqh[LAYERS * DDIM * DDIM];
__device__ bf16 g_Wql[LAYERS * DDIM * DDIM];
__device__ bf16 g_Wkh[LAYERS * DDIM * DDIM];
__device__ bf16 g_Wkl[LAYERS * DDIM * DDIM];
__device__ bf16 g_Wvh[LAYERS * DDIM * DDIM];
__device__ bf16 g_Wvl[LAYERS * DDIM * DDIM];
__device__ bf16 g_W1h[LAYERS * DDIM * FFDIM];
__device__ bf16 g_W1l[LAYERS * DDIM * FFDIM];
__device__ bf16 g_W2h[LAYERS * DDIM * FFDIM];
__device__ bf16 g_W2l[LAYERS * DDIM * FFDIM];

__device__ float g_zero_bias[DDIM];   // zero-initialized

// ================= helpers =================
__device__ __forceinline__ uint32_t packbf(bf16 a, bf16 b) {
    __nv_bfloat162 t = __nv_bfloat162(a, b);
    return *reinterpret_cast<uint32_t*>(&t);
}
__device__ __forceinline__ void split1(float v, bf16& h, bf16& l) {
    h = __float2bfloat16(v);
    l = __float2bfloat16(v - __bfloat162float(h));
}
__device__ __forceinline__ void split4(float4 v, uint2& hi, uint2& lo) {
    bf16 h0, l0, h1, l1, h2, l2, h3, l3;
    split1(v.x, h0, l0); split1(v.y, h1, l1);
    split1(v.z, h2, l2); split1(v.w, h3, l3);
    hi.x = packbf(h0, h1); hi.y = packbf(h2, h3);
    lo.x = packbf(l0, l1); lo.y = packbf(l2, l3);
}
__device__ __forceinline__ void ldsm_x4(uint32_t* r, uint32_t addr) {
    asm volatile("ldmatrix.sync.aligned.m8n8.x4.shared.b16 {%0,%1,%2,%3}, [%4];\n"
        : "=r"(r[0]), "=r"(r[1]), "=r"(r[2]), "=r"(r[3]) : "r"(addr));
}
__device__ __forceinline__ void ldsm_x4_t(uint32_t* r, uint32_t addr) {
    asm volatile("ldmatrix.sync.aligned.m8n8.x4.trans.shared.b16 {%0,%1,%2,%3}, [%4];\n"
        : "=r"(r[0]), "=r"(r[1]), "=r"(r[2]), "=r"(r[3]) : "r"(addr));
}
__device__ __forceinline__ void mma_bf16(float* c, const uint32_t* a, const uint32_t* b) {
    asm volatile("mma.sync.aligned.m16n8k16.row.col.f32.bf16.bf16.f32 "
        "{%0,%1,%2,%3}, {%4,%5,%6,%7}, {%8,%9}, {%0,%1,%2,%3};\n"
        : "+f"(c[0]), "+f"(c[1]), "+f"(c[2]), "+f"(c[3])
        : "r"(a[0]), "r"(a[1]), "r"(a[2]), "r"(a[3]), "r"(b[0]), "r"(b[1]));
}
__device__ __forceinline__ void cpa16s(void* dst, const void* src, int sz) {
    uint32_t d = (uint32_t)__cvta_generic_to_shared(dst);
    asm volatile("cp.async.cg.shared.global [%0], [%1], 16, %2;\n"
        :: "r"(d), "l"(src), "r"(sz));
}
__device__ __forceinline__ void cp_commit() {
    asm volatile("cp.async.commit_group;\n");
}
template<int N>
__device__ __forceinline__ void cp_wait() {
    asm volatile("cp.async.wait_group %0;\n" :: "n"(N));
}

// smem XOR swizzles (conflict-free for ldmatrix, 16B-aligned for cp.async)
__device__ __forceinline__ int swzA(int row, int col) {   // 32 cols
    int chunk = (col >> 3) ^ ((row >> 1) & 3);
    return row * 32 + chunk * 8;
}
__device__ __forceinline__ int swzB(int row, int col) {   // 64 cols
    int chunk = (col >> 3) ^ (row & 7);
    return row * 64 + chunk * 8;
}

// ================= fused weight split (all 5 weights, one launch) =================
__global__ __launch_bounds__(256)
void convw_all_kernel(const float4* __restrict__ Wq, const float4* __restrict__ Wk,
                      const float4* __restrict__ Wv, const float4* __restrict__ W1,
                      const float4* __restrict__ W2,
                      bf16* __restrict__ Wqh, bf16* __restrict__ Wql,
                      bf16* __restrict__ Wkh, bf16* __restrict__ Wkl,
                      bf16* __restrict__ Wvh, bf16* __restrict__ Wvl,
                      bf16* __restrict__ W1h, bf16* __restrict__ W1l,
                      bf16* __restrict__ W2h, bf16* __restrict__ W2l,
                      int nqkv4, int nff4)
{
    const float4* src;
    bf16 *h, *l;
    int n4;
    switch (blockIdx.y) {
        case 0: src = Wq; h = Wqh; l = Wql; n4 = nqkv4; break;
        case 1: src = Wk; h = Wkh; l = Wkl; n4 = nqkv4; break;
        case 2: src = Wv; h = Wvh; l = Wvl; n4 = nqkv4; break;
        case 3: src = W1; h = W1h; l = W1l; n4 = nff4;  break;
        default: src = W2; h = W2h; l = W2l; n4 = nff4;  break;
    }
    int stride = gridDim.x * blockDim.x;
    for (int idx = blockIdx.x * blockDim.x + threadIdx.x; idx < n4; idx += stride) {
        float4 v = src[idx];
        uint2 hi, lo;
        split4(v, hi, lo);
        *(uint2*)&h[idx * 4] = hi;
        *(uint2*)&l[idx * 4] = lo;
    }
}

// ================= embedding =================
__global__ void embed_kernel(const int* __restrict__ ids,
                             const float* __restrict__ memory,
                             const float* __restrict__ emb,
                             const float* __restrict__ pos,
                             float* __restrict__ x,
                             bf16* __restrict__ xh, bf16* __restrict__ xl)
{
    int idx = blockIdx.x * blockDim.x + threadIdx.x;
    if (idx >= TTOT * DDIM) return;
    int t = idx / DDIM;
    int d = idx - t * DDIM;
    float val;
    if (t < NB * MMEM) {
        val = memory[idx] + pos[(t & 1) * DDIM + d];
    } else {
        int tt = t - NB * MMEM;
        int tok = ids[tt];
        val = emb[(size_t)tok * DDIM + d] + pos[(MMEM + (tt & (LSEQ - 1))) * DDIM + d];
    }
    x[idx] = val;
    bf16 h, l;
    split1(val, h, l);
    xh[idx] = h; xl[idx] = l;
}

// ================= pipelined bf16x3 GEMM (proven R7 config) =================
// BM=128, BN=64, BK=32; 256 threads = 8 warps (4m x 2n), warptile 32x32.

struct __align__(16) SmemGemm {
    bf16 Ah[2][128 * 32];
    bf16 Al[2][128 * 32];
    bf16 Bh[2][32 * 64];
    bf16 Bl[2][32 * 64];
};

template<int ACT>
__device__ __forceinline__ void gemm_core(
    const bf16* __restrict__ Agh, const bf16* __restrict__ Agl,
    const bf16* __restrict__ Bgh, const bf16* __restrict__ Bgl,
    const float* __restrict__ bias,
    float* __restrict__ C, bf16* __restrict__ Ch, bf16* __restrict__ Cl,
    int Mr, int K, int Nc, int row0, int col0, int kStart, int kLen)
{
    __shared__ SmemGemm s;

    int tid = threadIdx.x;
    int lane = tid & 31;
    int wid = tid >> 5;
    int wm = wid & 3;
    int wn = wid >> 2;
    int lrow = lane & 15;
    int lcol8 = (lane >> 4) * 8;

    float acc[2][4][4];
    #pragma unroll
    for (int im = 0; im < 2; im++)
        #pragma unroll
        for (int in = 0; in < 4; in++)
            #pragma unroll
            for (int r = 0; r < 4; r++) acc[im][in][r] = 0.f;

    int arow = tid >> 2;
    int acol = (tid & 3) * 8;
    int brow = tid >> 3;
    int bcol = (tid & 7) * 8;

    auto load_stage = [&](int st, int k0) {
        #pragma unroll
        for (int i = 0; i < 2; i++) {
            int row = arow + i * 64;
            int grow = row0 + row;
            int ok = (grow < Mr) ? 16 : 0;
            int gr = (grow < Mr) ? grow : 0;
            const bf16* sh = &Agh[(size_t)gr * K + kStart + k0 + acol];
            const bf16* sl = &Agl[(size_t)gr * K + kStart + k0 + acol];
            cpa16s(&s.Ah[st][swzA(row, acol)], sh, ok);
            cpa16s(&s.Al[st][swzA(row, acol)], sl, ok);
        }
        cpa16s(&s.Bh[st][swzB(brow, bcol)],
               &Bgh[(size_t)(kStart + k0 + brow) * Nc + col0 + bcol], 16);
        cpa16s(&s.Bl[st][swzB(brow, bcol)],
               &Bgl[(size_t)(kStart + k0 + brow) * Nc + col0 + bcol], 16);
        cp_commit();
    };

    int nit = kLen / 32;
    load_stage(0, 0);

    for (int iter = 0; iter < nit; iter++) {
        int st = iter & 1;
        if (iter + 1 < nit) {
            load_stage(st ^ 1, (iter + 1) * 32);
            cp_wait<1>();
        } else {
            cp_wait<0>();
        }
        __syncthreads();

        #pragma unroll
        for (int ks = 0; ks < 32; ks += 16) {
            uint32_t ah[2][4], al[2][4];
            #pragma unroll
            for (int im = 0; im < 2; im++) {
                int mrow = wm * 32 + im * 16 + lrow;
                int mcol = ks + lcol8;
                ldsm_x4(ah[im], (uint32_t)__cvta_generic_to_shared(&s.Ah[st][swzA(mrow, mcol)]));
                ldsm_x4(al[im], (uint32_t)__cvta_generic_to_shared(&s.Al[st][swzA(mrow, mcol)]));
            }
            uint32_t bh[4][2], bl[4][2];
            #pragma unroll
            for (int g = 0; g < 2; g++) {
                int br = ks + lrow;
                int bc = wn * 32 + g * 16 + lcol8;
                uint32_t t[4];
                ldsm_x4_t(t, (uint32_t)__cvta_generic_to_shared(&s.Bh[st][swzB(br, bc)]));
                bh[2*g][0] = t[0]; bh[2*g][1] = t[1]; bh[2*g+1][0] = t[2]; bh[2*g+1][1] = t[3];
                ldsm_x4_t(t, (uint32_t)__cvta_generic_to_shared(&s.Bl[st][swzB(br, bc)]));
                bl[2*g][0] = t[0]; bl[2*g][1] = t[1]; bl[2*g+1][0] = t[2]; bl[2*g+1][1] = t[3];
            }
            #pragma unroll
            for (int im = 0; im < 2; im++)
                #pragma unroll
                for (int in = 0; in < 4; in++) {
                    mma_bf16(acc[im][in], ah[im], bh[in]);
                    mma_bf16(acc[im][in], ah[im], bl[in]);
                    mma_bf16(acc[im][in], al[im], bh[in]);
                }
        }
        __syncthreads();
    }

    #pragma unroll
    for (int im = 0; im < 2; im++) {
        int rbase = row0 + wm * 32 + im * 16 + (lane >> 2);
        #pragma unroll
        for (int in = 0; in < 4; in++) {
            int cc = col0 + wn * 32 + in * 8 + (lane & 3) * 2;
            float bs0 = bias[cc], bs1 = bias[cc + 1];
            #pragma unroll
            for (int half = 0; half < 2; half++) {
                int r = rbase + half * 8;
                if (r >= Mr) continue;
                float v0 = acc[im][in][half * 2 + 0] + bs0;
                float v1 = acc[im][in][half * 2 + 1] + bs1;
                if (ACT == 1) {
                    v0 = 0.5f * v0 * (1.f + erff(v0 * 0.70710678118654752f));
                    v1 = 0.5f * v1 * (1.f + erff(v1 * 0.70710678118654752f));
                    bf16 h0, l0, h1, l1;
                    split1(v0, h0, l0); split1(v1, h1, l1);
                    *(uint32_t*)&Ch[(size_t)r * Nc + cc] = packbf(h0, h1);
                    *(uint32_t*)&Cl[(size_t)r * Nc + cc] = packbf(l0, l1);
                } else {
                    *(float2*)&C[(size_t)r * Nc + cc] = make_float2(v0, v1);
                }
            }
        }
    }
}

__global__ __launch_bounds__(256)
void qkv_gemm_kernel(const bf16* __restrict__ xh, const bf16* __restrict__ xl,
                     const bf16* __restrict__ Wqh, const bf16* __restrict__ Wql,
                     const bf16* __restrict__ Wkh, const bf16* __restrict__ Wkl,
                     const bf16* __restrict__ Wvh, const bf16* __restrict__ Wvl,
                     const float* __restrict__ bq, const float* __restrict__ bk,
                     const float* __restrict__ bv,
                     float* __restrict__ q, float* __restrict__ k, float* __restrict__ v)
{
    const bf16 *Wh, *Wl; const float* b; float* o;
    if (blockIdx.z == 0)      { Wh = Wqh; Wl = Wql; b = bq; o = q; }
    else if (blockIdx.z == 1) { Wh = Wkh; Wl = Wkl; b = bk; o = k; }
    else                      { Wh = Wvh; Wl = Wvl; b = bv; o = v; }
    gemm_core<0>(xh, xl, Wh, Wl, b, o, nullptr, nullptr,
                 TTOT, DDIM, DDIM, blockIdx.y * 128, blockIdx.x * 64, 0, DDIM);
}

__global__ __launch_bounds__(256)
void ff1_gemm_kernel(const bf16* __restrict__ xh, const bf16* __restrict__ xl,
                     const bf16* __restrict__ W1h, const bf16* __restrict__ W1l,
                     const float* __restrict__ b1,
                     bf16* __restrict__ hh, bf16* __restrict__ hl)
{
    gemm_core<1>(xh, xl, W1h, W1l, b1, nullptr, hh, hl,
                 TTOT, DDIM, FFDIM, blockIdx.y * 128, blockIdx.x * 64, 0, DDIM);
}

__global__ __launch_bounds__(256)
void ff2_gemm_kernel(const bf16* __restrict__ hh, const bf16* __restrict__ hl,
                     const bf16* __restrict__ W2h, const bf16* __restrict__ W2l,
                     const float* __restrict__ b2,
                     float* __restrict__ ctx, float* __restrict__ p1)
{
    int z = blockIdx.z;
    const float* b = (z == 0) ? b2 : g_zero_bias;
    float* o = (z == 0) ? ctx : p1;
    gemm_core<0>(hh, hl, W2h, W2l, b, o, nullptr, nullptr,
                 TTOT, FFDIM, DDIM, blockIdx.y * 128, blockIdx.x * 64,
                 z * (FFDIM / 2), FFDIM / 2);
}

// ================= attention: block per (batch, head, qhalf) =================
#define QG 129
#define ATTN_THREADS 160
#define ATTN_SMEM (2 * KKEYS * 64 * 4)

__global__ __launch_bounds__(ATTN_THREADS)
void attn_kernel(const float* __restrict__ q, const float* __restrict__ k,
                 const float* __restrict__ v, float* __restrict__ ctx)
{
    extern __shared__ float asm_[];
    float* Ks = asm_;
    float* Vs = asm_ + KKEYS * 64;

    int b = blockIdx.x;
    int h = blockIdx.y;
    int zg = blockIdx.z;
    int tid = threadIdx.x;

    for (int i = tid; i < KKEYS * 16; i += ATTN_THREADS) {
        int j = i >> 4, c = i & 15;
        int key = (j < MMEM) ? (2 * b + j) : (8 + b * LSEQ + (j - MMEM));
        size_t off = (size_t)key * DDIM + h * 64 + c * 4;
        ((float4*)Ks)[i] = *(const float4*)&k[off];
        ((float4*)Vs)[i] = *(const float4*)&v[off];
    }
    __syncthreads();

    int qi = zg * QG + tid;
    if (tid < QG && qi < KKEYS) {
        int t = (qi < MMEM) ? (2 * b + qi) : (8 + b * LSEQ + (qi - MMEM));
        size_t qoff = (size_t)t * DDIM + h * 64;

        float4 qr[16];
        #pragma unroll
        for (int i = 0; i < 16; i++) {
            float4 qv = *(const float4*)&q[qoff + i * 4];
            qr[i] = make_float4(qv.x * 0.125f, qv.y * 0.125f, qv.z * 0.125f, qv.w * 0.125f);
        }

        float4 acc[16];
        #pragma unroll
        for (int i = 0; i < 16; i++) acc[i] = make_float4(0.f, 0.f, 0.f, 0.f);
        float l = 0.f;

        for (int j = 0; j < KKEYS; j++) {
            const float4* kr = (const float4*)(Ks + j * 64);
            // 4 independent partial sums -> dependency chain / 4
            float s0 = 0.f, s1 = 0.f, s2 = 0.f, s3 = 0.f;
            #pragma unroll
            for (int i = 0; i < 16; i += 4) {
                float4 k0 = kr[i], k1 = kr[i+1], k2 = kr[i+2], k3 = kr[i+3];
                s0 += qr[i].x * k0.x + qr[i].y * k0.y + qr[i].z * k0.z + qr[i].w * k0.w;
                s1 += qr[i+1].x * k1.x + qr[i+1].y * k1.y + qr[i+1].z * k1.z + qr[i+1].w * k1.w;
                s2 += qr[i+2].x * k2.x + qr[i+2].y * k2.y + qr[i+2].z * k2.z + qr[i+2].w * k2.w;
                s3 += qr[i+3].x * k3.x + qr[i+3].y * k3.y + qr[i+3].z * k3.z + qr[i+3].w * k3.w;
            }
            float p = __expf((s0 + s1) + (s2 + s3));
            l += p;
            const float4* vr = (const float4*)(Vs + j * 64);
            #pragma unroll
            for (int i = 0; i < 16; i++) {
                float4 vv = vr[i];
                acc[i].x += p * vv.x; acc[i].y += p * vv.y;
                acc[i].z += p * vv.z; acc[i].w += p * vv.w;
            }
        }

        float inv = 1.f / l;
        #pragma unroll
        for (int i = 0; i < 16; i++) {
            float4 o = make_float4(acc[i].x * inv, acc[i].y * inv,
                                   acc[i].z * inv, acc[i].w * inv);
            *(float4*)&ctx[qoff + i * 4] = o;
        }
    }
}

// ================= residual add + LN (warp per token) =================
// optional r2 (split-K partial) and optional out (final output rows 8+)
__global__ __launch_bounds__(256)
void add_ln_kernel(float* __restrict__ x, const float* __restrict__ r,
                   const float* __restrict__ r2,
                   const float* __restrict__ g, const float* __restrict__ b,
                   bf16* __restrict__ xh, bf16* __restrict__ xl,
                   float* __restrict__ out)
{
    int wid = threadIdx.x >> 5;
    int lane = threadIdx.x & 31;
    int t = blockIdx.x * 8 + wid;
    if (t >= TTOT) return;

    const float4* xp = (const float4*)(x + (size_t)t * DDIM);
    const float4* rp = (const float4*)(r + (size_t)t * DDIM);
    const float4* r2p = r2 ? (const float4*)(r2 + (size_t)t * DDIM) : nullptr;
    const float4* gp = (const float4*)g;
    const float4* bp = (const float4*)b;

    float4 v[6];
    float sum = 0.f;
    #pragma unroll
    for (int i = 0; i < 6; i++) {
        int idx = lane + i * 32;
        float4 a = xp[idx], c = rp[idx];
        v[i] = make_float4(a.x + c.x, a.y + c.y, a.z + c.z, a.w + c.w);
        if (r2p) {
            float4 e = r2p[idx];
            v[i].x += e.x; v[i].y += e.y; v[i].z += e.z; v[i].w += e.w;
        }
        sum += v[i].x + v[i].y + v[i].z + v[i].w;
    }
    #pragma unroll
    for (int o = 16; o > 0; o >>= 1) sum += __shfl_xor_sync(0xffffffffu, sum, o);
    float mu = sum * (1.f / DDIM);

    float var = 0.f;
    #pragma unroll
    for (int i = 0; i < 6; i++) {
        float dx = v[i].x - mu, dy = v[i].y - mu, dz = v[i].z - mu, dw = v[i].w - mu;
        var += dx * dx + dy * dy + dz * dz + dw * dw;
    }
    #pragma unroll
    for (int o = 16; o > 0; o >>= 1) var += __shfl_xor_sync(0xffffffffu, var, o);
    float rstd = rsqrtf(var * (1.f / DDIM) + 1e-5f);

    float4* xo = (float4*)(x + (size_t)t * DDIM);
    float4* oo = (out && t >= NB * MMEM)
               ? (float4*)(out + (size_t)(t - NB * MMEM) * DDIM) : nullptr;
    #pragma unroll
    for (int i = 0; i < 6; i++) {
        int idx = lane + i * 32;
        float4 gg = gp[idx], bb = bp[idx];
        float4 o;
        o.x = (v[i].x - mu) * rstd * gg.x + bb.x;
        o.y = (v[i].y - mu) * rstd * gg.y + bb.y;
        o.z = (v[i].z - mu) * rstd * gg.z + bb.z;
        o.w = (v[i].w - mu) * rstd * gg.w + bb.w;
        xo[idx] = o;
        if (oo) oo[idx] = o;
        uint2 hi, lo;
        split4(o, hi, lo);
        *(uint2*)&xh[(size_t)t * DDIM + idx * 4] = hi;
        *(uint2*)&xl[(size_t)t * DDIM + idx * 4] = lo;
    }
}

extern "C" void kernel_launch(void* const* d_in, const int* in_sizes, int n_in,
                              void* d_out, int out_size)
{
    const int*   ids    = (const int*)  d_in[0];
    const float* memory = (const float*)d_in[1];
    const float* emb    = (const float*)d_in[2];
    const float* pos    = (const float*)d_in[3];
    const float* Wq     = (const float*)d_in[4];
    const float* bq     = (const float*)d_in[5];
    const float* Wk     = (const float*)d_in[6];
    const float* bk     = (const float*)d_in[7];
    const float* Wv     = (const float*)d_in[8];
    const float* bv     = (const float*)d_in[9];
    const float* W1     = (const float*)d_in[10];
    const float* b1     = (const float*)d_in[11];
    const float* W2     = (const float*)d_in[12];
    const float* b2     = (const float*)d_in[13];
    const float* g1     = (const float*)d_in[14];
    const float* be1    = (const float*)d_in[15];
    const float* g2     = (const float*)d_in[16];
    const float* be2    = (const float*)d_in[17];
    float* out = (float*)d_out;

    float *x, *q, *k, *v, *ctx, *p1;
    bf16 *xh, *xl, *hh, *hl;
    bf16 *Wqh, *Wql, *Wkh, *Wkl, *Wvh, *Wvl, *W1h, *W1l, *W2h, *W2l;
    cudaGetSymbolAddress((void**)&x,   g_x);
    cudaGetSymbolAddress((void**)&q,   g_q);
    cudaGetSymbolAddress((void**)&k,   g_k);
    cudaGetSymbolAddress((void**)&v,   g_v);
    cudaGetSymbolAddress((void**)&ctx, g_ctx);
    cudaGetSymbolAddress((void**)&p1,  g_p1);
    cudaGetSymbolAddress((void**)&xh,  g_xh);
    cudaGetSymbolAddress((void**)&xl,  g_xl);
    cudaGetSymbolAddress((void**)&hh,  g_hh);
    cudaGetSymbolAddress((void**)&hl,  g_hl);
    cudaGetSymbolAddress((void**)&Wqh, g_Wqh);
    cudaGetSymbolAddress((void**)&Wql, g_Wql);
    cudaGetSymbolAddress((void**)&Wkh, g_Wkh);
    cudaGetSymbolAddress((void**)&Wkl, g_Wkl);
    cudaGetSymbolAddress((void**)&Wvh, g_Wvh);
    cudaGetSymbolAddress((void**)&Wvl, g_Wvl);
    cudaGetSymbolAddress((void**)&W1h, g_W1h);
    cudaGetSymbolAddress((void**)&W1l, g_W1l);
    cudaGetSymbolAddress((void**)&W2h, g_W2h);
    cudaGetSymbolAddress((void**)&W2l, g_W2l);

    cudaFuncSetAttribute(attn_kernel, cudaFuncAttributeMaxDynamicSharedMemorySize, ATTN_SMEM);

    int nqkv4 = LAYERS * DDIM * DDIM / 4;       // 589824
    int nff4  = LAYERS * DDIM * FFDIM / 4;      // 2359296

    embed_kernel<<<(TTOT * DDIM + 255) / 256, 256>>>(ids, memory, emb, pos, x, xh, xl);
    convw_all_kernel<<<dim3(2304, 5), 256>>>(
        (const float4*)Wq, (const float4*)Wk, (const float4*)Wv,
        (const float4*)W1, (const float4*)W2,
        Wqh, Wql, Wkh, Wkl, Wvh, Wvl, W1h, W1l, W2h, W2l,
        nqkv4, nff4);

    const int MB = (TTOT + 127) / 128;          // 9
    dim3 grid_qkv(DDIM / 64, MB, 3);            // (12, 9, 3)
    dim3 grid_ff1(FFDIM / 64, MB);              // (48, 9)
    dim3 grid_ff2(DDIM / 64, MB, 2);            // (12, 9, 2) split-K
    dim3 grid_attn(NB, HNUM, 2);                // (4, 12, 2)
    int ln_grid = (TTOT + 7) / 8;               // 129

    for (int i = 0; i < LAYERS; i++) {
        size_t od = (size_t)i * DDIM * DDIM;
        size_t of = (size_t)i * DDIM * FFDIM;
        qkv_gemm_kernel<<<grid_qkv, 256>>>(
            xh, xl,
            Wqh + od, Wql + od, Wkh + od, Wkl + od, Wvh + od, Wvl + od,
            bq + i * DDIM, bk + i * DDIM, bv + i * DDIM,
            q, k, v);

        attn_kernel<<<grid_attn, ATTN_THREADS, ATTN_SMEM>>>(q, k, v, ctx);

        add_ln_kernel<<<ln_grid, 256>>>(x, ctx, nullptr,
                                        g1 + i * DDIM, be1 + i * DDIM, xh, xl, nullptr);

        ff1_gemm_kernel<<<grid_ff1, 256>>>(xh, xl, W1h + of, W1l + of,
                                           b1 + i * FFDIM, hh, hl);
        ff2_gemm_kernel<<<grid_ff2, 256>>>(hh, hl, W2h + of, W2l + of,
                                           b2 + i * DDIM, ctx, p1);

        add_ln_kernel<<<ln_grid, 256>>>(x, ctx, p1,
                                        g2 + i * DDIM, be2 + i * DDIM, xh, xl,
                                        (i == LAYERS - 1) ? out : nullptr);
    }
}

// round 15
// speedup vs baseline: 1.8767x; 1.0526x over previous
#include <cuda_runtime.h>
#include <cuda_bf16.h>
#include <math.h>
#include <stdint.h>

// Problem constants
#define NB 4
#define LSEQ 256
#define MMEM 2
#define DDIM 768
#define HNUM 12
#define FFDIM 3072
#define LAYERS 4
#define TTOT 1032
#define KKEYS 258

typedef __nv_bfloat16 bf16;

// -------- scratch (device globals) --------
__device__ float g_x[TTOT * DDIM];
__device__ float g_q[TTOT * DDIM];
__device__ float g_k[TTOT * DDIM];
__device__ float g_v[TTOT * DDIM];
__device__ float g_ctx[TTOT * DDIM];
__device__ float g_p1[TTOT * DDIM];

__device__ bf16 g_xh[TTOT * DDIM];
__device__ bf16 g_xl[TTOT * DDIM];
__device__ bf16 g_hh[TTOT * FFDIM];
__device__ bf16 g_hl[TTOT * FFDIM];

// pre-split weights (bf16 hi/lo, original [K][N] row-major layout)
__device__ bf16 g_Wqh[LAYERS * DDIM * DDIM];
__device__ bf16 g_Wql[LAYERS * DDIM * DDIM];
__device__ bf16 g_Wkh[LAYERS * DDIM * DDIM];
__device__ bf16 g_Wkl[LAYERS * DDIM * DDIM];
__device__ bf16 g_Wvh[LAYERS * DDIM * DDIM];
__device__ bf16 g_Wvl[LAYERS * DDIM * DDIM];
__device__ bf16 g_W1h[LAYERS * DDIM * FFDIM];
__device__ bf16 g_W1l[LAYERS * DDIM * FFDIM];
__device__ bf16 g_W2h[LAYERS * DDIM * FFDIM];
__device__ bf16 g_W2l[LAYERS * DDIM * FFDIM];

__device__ float g_zero_bias[DDIM];   // zero-initialized

// ================= helpers =================
__device__ __forceinline__ uint32_t packbf(bf16 a, bf16 b) {
    __nv_bfloat162 t = __nv_bfloat162(a, b);
    return *reinterpret_cast<uint32_t*>(&t);
}
__device__ __forceinline__ void split1(float v, bf16& h, bf16& l) {
    h = __float2bfloat16(v);
    l = __float2bfloat16(v - __bfloat162float(h));
}
__device__ __forceinline__ void split4(float4 v, uint2& hi, uint2& lo) {
    bf16 h0, l0, h1, l1, h2, l2, h3, l3;
    split1(v.x, h0, l0); split1(v.y, h1, l1);
    split1(v.z, h2, l2); split1(v.w, h3, l3);
    hi.x = packbf(h0, h1); hi.y = packbf(h2, h3);
    lo.x = packbf(l0, l1); lo.y = packbf(l2, l3);
}
__device__ __forceinline__ void ldsm_x4(uint32_t* r, uint32_t addr) {
    asm volatile("ldmatrix.sync.aligned.m8n8.x4.shared.b16 {%0,%1,%2,%3}, [%4];\n"
        : "=r"(r[0]), "=r"(r[1]), "=r"(r[2]), "=r"(r[3]) : "r"(addr));
}
__device__ __forceinline__ void ldsm_x4_t(uint32_t* r, uint32_t addr) {
    asm volatile("ldmatrix.sync.aligned.m8n8.x4.trans.shared.b16 {%0,%1,%2,%3}, [%4];\n"
        : "=r"(r[0]), "=r"(r[1]), "=r"(r[2]), "=r"(r[3]) : "r"(addr));
}
__device__ __forceinline__ void mma_bf16(float* c, const uint32_t* a, const uint32_t* b) {
    asm volatile("mma.sync.aligned.m16n8k16.row.col.f32.bf16.bf16.f32 "
        "{%0,%1,%2,%3}, {%4,%5,%6,%7}, {%8,%9}, {%0,%1,%2,%3};\n"
        : "+f"(c[0]), "+f"(c[1]), "+f"(c[2]), "+f"(c[3])
        : "r"(a[0]), "r"(a[1]), "r"(a[2]), "r"(a[3]), "r"(b[0]), "r"(b[1]));
}
__device__ __forceinline__ void cpa16s(void* dst, const void* src, int sz) {
    uint32_t d = (uint32_t)__cvta_generic_to_shared(dst);
    asm volatile("cp.async.cg.shared.global [%0], [%1], 16, %2;\n"
        :: "r"(d), "l"(src), "r"(sz));
}
__device__ __forceinline__ void cp_commit() {
    asm volatile("cp.async.commit_group;\n");
}
template<int N>
__device__ __forceinline__ void cp_wait() {
    asm volatile("cp.async.wait_group %0;\n" :: "n"(N));
}

// smem XOR swizzles (conflict-free for ldmatrix, 16B-aligned for cp.async)
__device__ __forceinline__ int swzA(int row, int col) {   // 32 cols
    int chunk = (col >> 3) ^ ((row >> 1) & 3);
    return row * 32 + chunk * 8;
}
__device__ __forceinline__ int swzB(int row, int col) {   // 64 cols
    int chunk = (col >> 3) ^ (row & 7);
    return row * 64 + chunk * 8;
}

// ================= fused weight split (all 5 weights, one launch) =================
__global__ __launch_bounds__(256)
void convw_all_kernel(const float4* __restrict__ Wq, const float4* __restrict__ Wk,
                      const float4* __restrict__ Wv, const float4* __restrict__ W1,
                      const float4* __restrict__ W2,
                      bf16* __restrict__ Wqh, bf16* __restrict__ Wql,
                      bf16* __restrict__ Wkh, bf16* __restrict__ Wkl,
                      bf16* __restrict__ Wvh, bf16* __restrict__ Wvl,
                      bf16* __restrict__ W1h, bf16* __restrict__ W1l,
                      bf16* __restrict__ W2h, bf16* __restrict__ W2l,
                      int nqkv4, int nff4)
{
    const float4* src;
    bf16 *h, *l;
    int n4;
    switch (blockIdx.y) {
        case 0: src = Wq; h = Wqh; l = Wql; n4 = nqkv4; break;
        case 1: src = Wk; h = Wkh; l = Wkl; n4 = nqkv4; break;
        case 2: src = Wv; h = Wvh; l = Wvl; n4 = nqkv4; break;
        case 3: src = W1; h = W1h; l = W1l; n4 = nff4;  break;
        default: src = W2; h = W2h; l = W2l; n4 = nff4;  break;
    }
    int stride = gridDim.x * blockDim.x;
    for (int idx = blockIdx.x * blockDim.x + threadIdx.x; idx < n4; idx += stride) {
        float4 v = src[idx];
        uint2 hi, lo;
        split4(v, hi, lo);
        *(uint2*)&h[idx * 4] = hi;
        *(uint2*)&l[idx * 4] = lo;
    }
}

// ================= embedding =================
__global__ void embed_kernel(const int* __restrict__ ids,
                             const float* __restrict__ memory,
                             const float* __restrict__ emb,
                             const float* __restrict__ pos,
                             float* __restrict__ x,
                             bf16* __restrict__ xh, bf16* __restrict__ xl)
{
    int idx = blockIdx.x * blockDim.x + threadIdx.x;
    if (idx >= TTOT * DDIM) return;
    int t = idx / DDIM;
    int d = idx - t * DDIM;
    float val;
    if (t < NB * MMEM) {
        val = memory[idx] + pos[(t & 1) * DDIM + d];
    } else {
        int tt = t - NB * MMEM;
        int tok = ids[tt];
        val = emb[(size_t)tok * DDIM + d] + pos[(MMEM + (tt & (LSEQ - 1))) * DDIM + d];
    }
    x[idx] = val;
    bf16 h, l;
    split1(val, h, l);
    xh[idx] = h; xl[idx] = l;
}

// ================= pipelined bf16x3 GEMM (proven R7 config) =================
// BM=128, BN=64, BK=32; 256 threads = 8 warps (4m x 2n), warptile 32x32.

struct __align__(16) SmemGemm {
    bf16 Ah[2][128 * 32];
    bf16 Al[2][128 * 32];
    bf16 Bh[2][32 * 64];
    bf16 Bl[2][32 * 64];
};

template<int ACT>
__device__ __forceinline__ void gemm_core(
    const bf16* __restrict__ Agh, const bf16* __restrict__ Agl,
    const bf16* __restrict__ Bgh, const bf16* __restrict__ Bgl,
    const float* __restrict__ bias,
    float* __restrict__ C, bf16* __restrict__ Ch, bf16* __restrict__ Cl,
    int Mr, int K, int Nc, int row0, int col0, int kStart, int kLen)
{
    __shared__ SmemGemm s;

    int tid = threadIdx.x;
    int lane = tid & 31;
    int wid = tid >> 5;
    int wm = wid & 3;
    int wn = wid >> 2;
    int lrow = lane & 15;
    int lcol8 = (lane >> 4) * 8;

    float acc[2][4][4];
    #pragma unroll
    for (int im = 0; im < 2; im++)
        #pragma unroll
        for (int in = 0; in < 4; in++)
            #pragma unroll
            for (int r = 0; r < 4; r++) acc[im][in][r] = 0.f;

    int arow = tid >> 2;
    int acol = (tid & 3) * 8;
    int brow = tid >> 3;
    int bcol = (tid & 7) * 8;

    auto load_stage = [&](int st, int k0) {
        #pragma unroll
        for (int i = 0; i < 2; i++) {
            int row = arow + i * 64;
            int grow = row0 + row;
            int ok = (grow < Mr) ? 16 : 0;
            int gr = (grow < Mr) ? grow : 0;
            const bf16* sh = &Agh[(size_t)gr * K + kStart + k0 + acol];
            const bf16* sl = &Agl[(size_t)gr * K + kStart + k0 + acol];
            cpa16s(&s.Ah[st][swzA(row, acol)], sh, ok);
            cpa16s(&s.Al[st][swzA(row, acol)], sl, ok);
        }
        cpa16s(&s.Bh[st][swzB(brow, bcol)],
               &Bgh[(size_t)(kStart + k0 + brow) * Nc + col0 + bcol], 16);
        cpa16s(&s.Bl[st][swzB(brow, bcol)],
               &Bgl[(size_t)(kStart + k0 + brow) * Nc + col0 + bcol], 16);
        cp_commit();
    };

    int nit = kLen / 32;
    load_stage(0, 0);

    for (int iter = 0; iter < nit; iter++) {
        int st = iter & 1;
        if (iter + 1 < nit) {
            load_stage(st ^ 1, (iter + 1) * 32);
            cp_wait<1>();
        } else {
            cp_wait<0>();
        }
        __syncthreads();

        #pragma unroll
        for (int ks = 0; ks < 32; ks += 16) {
            uint32_t ah[2][4], al[2][4];
            #pragma unroll
            for (int im = 0; im < 2; im++) {
                int mrow = wm * 32 + im * 16 + lrow;
                int mcol = ks + lcol8;
                ldsm_x4(ah[im], (uint32_t)__cvta_generic_to_shared(&s.Ah[st][swzA(mrow, mcol)]));
                ldsm_x4(al[im], (uint32_t)__cvta_generic_to_shared(&s.Al[st][swzA(mrow, mcol)]));
            }
            uint32_t bh[4][2], bl[4][2];
            #pragma unroll
            for (int g = 0; g < 2; g++) {
                int br = ks + lrow;
                int bc = wn * 32 + g * 16 + lcol8;
                uint32_t t[4];
                ldsm_x4_t(t, (uint32_t)__cvta_generic_to_shared(&s.Bh[st][swzB(br, bc)]));
                bh[2*g][0] = t[0]; bh[2*g][1] = t[1]; bh[2*g+1][0] = t[2]; bh[2*g+1][1] = t[3];
                ldsm_x4_t(t, (uint32_t)__cvta_generic_to_shared(&s.Bl[st][swzB(br, bc)]));
                bl[2*g][0] = t[0]; bl[2*g][1] = t[1]; bl[2*g+1][0] = t[2]; bl[2*g+1][1] = t[3];
            }
            #pragma unroll
            for (int im = 0; im < 2; im++)
                #pragma unroll
                for (int in = 0; in < 4; in++) {
                    mma_bf16(acc[im][in], ah[im], bh[in]);
                    mma_bf16(acc[im][in], ah[im], bl[in]);
                    mma_bf16(acc[im][in], al[im], bh[in]);
                }
        }
        __syncthreads();
    }

    #pragma unroll
    for (int im = 0; im < 2; im++) {
        int rbase = row0 + wm * 32 + im * 16 + (lane >> 2);
        #pragma unroll
        for (int in = 0; in < 4; in++) {
            int cc = col0 + wn * 32 + in * 8 + (lane & 3) * 2;
            float bs0 = bias[cc], bs1 = bias[cc + 1];
            #pragma unroll
            for (int half = 0; half < 2; half++) {
                int r = rbase + half * 8;
                if (r >= Mr) continue;
                float v0 = acc[im][in][half * 2 + 0] + bs0;
                float v1 = acc[im][in][half * 2 + 1] + bs1;
                if (ACT == 1) {
                    v0 = 0.5f * v0 * (1.f + erff(v0 * 0.70710678118654752f));
                    v1 = 0.5f * v1 * (1.f + erff(v1 * 0.70710678118654752f));
                    bf16 h0, l0, h1, l1;
                    split1(v0, h0, l0); split1(v1, h1, l1);
                    *(uint32_t*)&Ch[(size_t)r * Nc + cc] = packbf(h0, h1);
                    *(uint32_t*)&Cl[(size_t)r * Nc + cc] = packbf(l0, l1);
                } else {
                    *(float2*)&C[(size_t)r * Nc + cc] = make_float2(v0, v1);
                }
            }
        }
    }
}

__global__ __launch_bounds__(256)
void qkv_gemm_kernel(const bf16* __restrict__ xh, const bf16* __restrict__ xl,
                     const bf16* __restrict__ Wqh, const bf16* __restrict__ Wql,
                     const bf16* __restrict__ Wkh, const bf16* __restrict__ Wkl,
                     const bf16* __restrict__ Wvh, const bf16* __restrict__ Wvl,
                     const float* __restrict__ bq, const float* __restrict__ bk,
                     const float* __restrict__ bv,
                     float* __restrict__ q, float* __restrict__ k, float* __restrict__ v)
{
    const bf16 *Wh, *Wl; const float* b; float* o;
    if (blockIdx.z == 0)      { Wh = Wqh; Wl = Wql; b = bq; o = q; }
    else if (blockIdx.z == 1) { Wh = Wkh; Wl = Wkl; b = bk; o = k; }
    else                      { Wh = Wvh; Wl = Wvl; b = bv; o = v; }
    gemm_core<0>(xh, xl, Wh, Wl, b, o, nullptr, nullptr,
                 TTOT, DDIM, DDIM, blockIdx.y * 128, blockIdx.x * 64, 0, DDIM);
}

__global__ __launch_bounds__(256)
void ff1_gemm_kernel(const bf16* __restrict__ xh, const bf16* __restrict__ xl,
                     const bf16* __restrict__ W1h, const bf16* __restrict__ W1l,
                     const float* __restrict__ b1,
                     bf16* __restrict__ hh, bf16* __restrict__ hl)
{
    gemm_core<1>(xh, xl, W1h, W1l, b1, nullptr, hh, hl,
                 TTOT, DDIM, FFDIM, blockIdx.y * 128, blockIdx.x * 64, 0, DDIM);
}

__global__ __launch_bounds__(256)
void ff2_gemm_kernel(const bf16* __restrict__ hh, const bf16* __restrict__ hl,
                     const bf16* __restrict__ W2h, const bf16* __restrict__ W2l,
                     const float* __restrict__ b2,
                     float* __restrict__ ctx, float* __restrict__ p1)
{
    int z = blockIdx.z;
    const float* b = (z == 0) ? b2 : g_zero_bias;
    float* o = (z == 0) ? ctx : p1;
    gemm_core<0>(hh, hl, W2h, W2l, b, o, nullptr, nullptr,
                 TTOT, FFDIM, DDIM, blockIdx.y * 128, blockIdx.x * 64,
                 z * (FFDIM / 2), FFDIM / 2);
}

// ================= attention: block per (batch, head, qhalf) =================
// 320 threads = 2 key-groups x 160. Group g handles keys [g*129,(g+1)*129).
// No-max softmax => partials (sum_e, sum_e*V) combine additively.
// Group 1 parks partials in the (dead-by-then) K buffer; group 0 merges.
#define QG 129
#define ATTN_THREADS 320
#define ATTN_SMEM (2 * KKEYS * 64 * 4)

__global__ __launch_bounds__(ATTN_THREADS)
void attn_kernel(const float* __restrict__ q, const float* __restrict__ k,
                 const float* __restrict__ v, float* __restrict__ ctx)
{
    extern __shared__ float asm_[];
    float* Ks = asm_;
    float* Vs = asm_ + KKEYS * 64;

    int b = blockIdx.x;
    int h = blockIdx.y;
    int zg = blockIdx.z;
    int tid = threadIdx.x;

    for (int i = tid; i < KKEYS * 16; i += ATTN_THREADS) {
        int j = i >> 4, c = i & 15;
        int key = (j < MMEM) ? (2 * b + j) : (8 + b * LSEQ + (j - MMEM));
        size_t off = (size_t)key * DDIM + h * 64 + c * 4;
        ((float4*)Ks)[i] = *(const float4*)&k[off];
        ((float4*)Vs)[i] = *(const float4*)&v[off];
    }
    __syncthreads();

    int g = tid / 160;             // key-group 0 or 1
    int qt = tid - g * 160;        // query slot within group
    int qi = zg * QG + qt;
    bool active = (qt < QG) && (qi < KKEYS);

    float4 acc[16];
    float l = 0.f;
    size_t qoff = 0;

    if (active) {
        int t = (qi < MMEM) ? (2 * b + qi) : (8 + b * LSEQ + (qi - MMEM));
        qoff = (size_t)t * DDIM + h * 64;

        float4 qr[16];
        #pragma unroll
        for (int i = 0; i < 16; i++) {
            float4 qv = *(const float4*)&q[qoff + i * 4];
            qr[i] = make_float4(qv.x * 0.125f, qv.y * 0.125f, qv.z * 0.125f, qv.w * 0.125f);
        }
        #pragma unroll
        for (int i = 0; i < 16; i++) acc[i] = make_float4(0.f, 0.f, 0.f, 0.f);

        int j0 = g * 129, j1 = j0 + 129;   // 0..129 | 129..258
        for (int j = j0; j < j1; j++) {
            const float4* kr = (const float4*)(Ks + j * 64);
            float s0 = 0.f, s1 = 0.f, s2 = 0.f, s3 = 0.f;
            #pragma unroll
            for (int i = 0; i < 16; i += 4) {
                float4 k0 = kr[i], k1 = kr[i+1], k2 = kr[i+2], k3 = kr[i+3];
                s0 += qr[i].x * k0.x + qr[i].y * k0.y + qr[i].z * k0.z + qr[i].w * k0.w;
                s1 += qr[i+1].x * k1.x + qr[i+1].y * k1.y + qr[i+1].z * k1.z + qr[i+1].w * k1.w;
                s2 += qr[i+2].x * k2.x + qr[i+2].y * k2.y + qr[i+2].z * k2.z + qr[i+2].w * k2.w;
                s3 += qr[i+3].x * k3.x + qr[i+3].y * k3.y + qr[i+3].z * k3.z + qr[i+3].w * k3.w;
            }
            float p = __expf((s0 + s1) + (s2 + s3));
            l += p;
            const float4* vr = (const float4*)(Vs + j * 64);
            #pragma unroll
            for (int i = 0; i < 16; i++) {
                float4 vv = vr[i];
                acc[i].x += p * vv.x; acc[i].y += p * vv.y;
                acc[i].z += p * vv.z; acc[i].w += p * vv.w;
            }
        }
    }

    __syncthreads();   // all key-reads from Ks complete; Ks reusable

    float* P = Ks;     // partial buffer: 129 x 65 floats (fits in K region)
    if (active && g == 1) {
        float* p = P + qt * 66;
        #pragma unroll
        for (int i = 0; i < 16; i++) {
            p[i * 4 + 0] = acc[i].x; p[i * 4 + 1] = acc[i].y;
            p[i * 4 + 2] = acc[i].z; p[i * 4 + 3] = acc[i].w;
        }
        p[64] = l;
    }
    __syncthreads();

    if (active && g == 0) {
        const float* p = P + qt * 66;
        #pragma unroll
        for (int i = 0; i < 16; i++) {
            acc[i].x += p[i * 4 + 0]; acc[i].y += p[i * 4 + 1];
            acc[i].z += p[i * 4 + 2]; acc[i].w += p[i * 4 + 3];
        }
        l += p[64];
        float inv = 1.f / l;
        #pragma unroll
        for (int i = 0; i < 16; i++) {
            float4 o = make_float4(acc[i].x * inv, acc[i].y * inv,
                                   acc[i].z * inv, acc[i].w * inv);
            *(float4*)&ctx[qoff + i * 4] = o;
        }
    }
}

// ================= residual add + LN (warp per token) =================
__global__ __launch_bounds__(256)
void add_ln_kernel(float* __restrict__ x, const float* __restrict__ r,
                   const float* __restrict__ r2,
                   const float* __restrict__ g, const float* __restrict__ b,
                   bf16* __restrict__ xh, bf16* __restrict__ xl,
                   float* __restrict__ out)
{
    int wid = threadIdx.x >> 5;
    int lane = threadIdx.x & 31;
    int t = blockIdx.x * 8 + wid;
    if (t >= TTOT) return;

    const float4* xp = (const float4*)(x + (size_t)t * DDIM);
    const float4* rp = (const float4*)(r + (size_t)t * DDIM);
    const float4* r2p = r2 ? (const float4*)(r2 + (size_t)t * DDIM) : nullptr;
    const float4* gp = (const float4*)g;
    const float4* bp = (const float4*)b;

    float4 v[6];
    float sum = 0.f;
    #pragma unroll
    for (int i = 0; i < 6; i++) {
        int idx = lane + i * 32;
        float4 a = xp[idx], c = rp[idx];
        v[i] = make_float4(a.x + c.x, a.y + c.y, a.z + c.z, a.w + c.w);
        if (r2p) {
            float4 e = r2p[idx];
            v[i].x += e.x; v[i].y += e.y; v[i].z += e.z; v[i].w += e.w;
        }
        sum += v[i].x + v[i].y + v[i].z + v[i].w;
    }
    #pragma unroll
    for (int o = 16; o > 0; o >>= 1) sum += __shfl_xor_sync(0xffffffffu, sum, o);
    float mu = sum * (1.f / DDIM);

    float var = 0.f;
    #pragma unroll
    for (int i = 0; i < 6; i++) {
        float dx = v[i].x - mu, dy = v[i].y - mu, dz = v[i].z - mu, dw = v[i].w - mu;
        var += dx * dx + dy * dy + dz * dz + dw * dw;
    }
    #pragma unroll
    for (int o = 16; o > 0; o >>= 1) var += __shfl_xor_sync(0xffffffffu, var, o);
    float rstd = rsqrtf(var * (1.f / DDIM) + 1e-5f);

    float4* xo = (float4*)(x + (size_t)t * DDIM);
    float4* oo = (out && t >= NB * MMEM)
               ? (float4*)(out + (size_t)(t - NB * MMEM) * DDIM) : nullptr;
    #pragma unroll
    for (int i = 0; i < 6; i++) {
        int idx = lane + i * 32;
        float4 gg = gp[idx], bb = bp[idx];
        float4 o;
        o.x = (v[i].x - mu) * rstd * gg.x + bb.x;
        o.y = (v[i].y - mu) * rstd * gg.y + bb.y;
        o.z = (v[i].z - mu) * rstd * gg.z + bb.z;
        o.w = (v[i].w - mu) * rstd * gg.w + bb.w;
        xo[idx] = o;
        if (oo) oo[idx] = o;
        uint2 hi, lo;
        split4(o, hi, lo);
        *(uint2*)&xh[(size_t)t * DDIM + idx * 4] = hi;
        *(uint2*)&xl[(size_t)t * DDIM + idx * 4] = lo;
    }
}

extern "C" void kernel_launch(void* const* d_in, const int* in_sizes, int n_in,
                              void* d_out, int out_size)
{
    const int*   ids    = (const int*)  d_in[0];
    const float* memory = (const float*)d_in[1];
    const float* emb    = (const float*)d_in[2];
    const float* pos    = (const float*)d_in[3];
    const float* Wq     = (const float*)d_in[4];
    const float* bq     = (const float*)d_in[5];
    const float* Wk     = (const float*)d_in[6];
    const float* bk     = (const float*)d_in[7];
    const float* Wv     = (const float*)d_in[8];
    const float* bv     = (const float*)d_in[9];
    const float* W1     = (const float*)d_in[10];
    const float* b1     = (const float*)d_in[11];
    const float* W2     = (const float*)d_in[12];
    const float* b2     = (const float*)d_in[13];
    const float* g1     = (const float*)d_in[14];
    const float* be1    = (const float*)d_in[15];
    const float* g2     = (const float*)d_in[16];
    const float* be2    = (const float*)d_in[17];
    float* out = (float*)d_out;

    float *x, *q, *k, *v, *ctx, *p1;
    bf16 *xh, *xl, *hh, *hl;
    bf16 *Wqh, *Wql, *Wkh, *Wkl, *Wvh, *Wvl, *W1h, *W1l, *W2h, *W2l;
    cudaGetSymbolAddress((void**)&x,   g_x);
    cudaGetSymbolAddress((void**)&q,   g_q);
    cudaGetSymbolAddress((void**)&k,   g_k);
    cudaGetSymbolAddress((void**)&v,   g_v);
    cudaGetSymbolAddress((void**)&ctx, g_ctx);
    cudaGetSymbolAddress((void**)&p1,  g_p1);
    cudaGetSymbolAddress((void**)&xh,  g_xh);
    cudaGetSymbolAddress((void**)&xl,  g_xl);
    cudaGetSymbolAddress((void**)&hh,  g_hh);
    cudaGetSymbolAddress((void**)&hl,  g_hl);
    cudaGetSymbolAddress((void**)&Wqh, g_Wqh);
    cudaGetSymbolAddress((void**)&Wql, g_Wql);
    cudaGetSymbolAddress((void**)&Wkh, g_Wkh);
    cudaGetSymbolAddress((void**)&Wkl, g_Wkl);
    cudaGetSymbolAddress((void**)&Wvh, g_Wvh);
    cudaGetSymbolAddress((void**)&Wvl, g_Wvl);
    cudaGetSymbolAddress((void**)&W1h, g_W1h);
    cudaGetSymbolAddress((void**)&W1l, g_W1l);
    cudaGetSymbolAddress((void**)&W2h, g_W2h);
    cudaGetSymbolAddress((void**)&W2l, g_W2l);

    cudaFuncSetAttribute(attn_kernel, cudaFuncAttributeMaxDynamicSharedMemorySize, ATTN_SMEM);

    int nqkv4 = LAYERS * DDIM * DDIM / 4;       // 589824
    int nff4  = LAYERS * DDIM * FFDIM / 4;      // 2359296

    embed_kernel<<<(TTOT * DDIM + 255) / 256, 256>>>(ids, memory, emb, pos, x, xh, xl);
    convw_all_kernel<<<dim3(2304, 5), 256>>>(
        (const float4*)Wq, (const float4*)Wk, (const float4*)Wv,
        (const float4*)W1, (const float4*)W2,
        Wqh, Wql, Wkh, Wkl, Wvh, Wvl, W1h, W1l, W2h, W2l,
        nqkv4, nff4);

    const int MB = (TTOT + 127) / 128;          // 9
    dim3 grid_qkv(DDIM / 64, MB, 3);            // (12, 9, 3)
    dim3 grid_ff1(FFDIM / 64, MB);              // (48, 9)
    dim3 grid_ff2(DDIM / 64, MB, 2);            // (12, 9, 2) split-K
    dim3 grid_attn(NB, HNUM, 2);                // (4, 12, 2)
    int ln_grid = (TTOT + 7) / 8;               // 129

    for (int i = 0; i < LAYERS; i++) {
        size_t od = (size_t)i * DDIM * DDIM;
        size_t of = (size_t)i * DDIM * FFDIM;
        qkv_gemm_kernel<<<grid_qkv, 256>>>(
            xh, xl,
            Wqh + od, Wql + od, Wkh + od, Wkl + od, Wvh + od, Wvl + od,
            bq + i * DDIM, bk + i * DDIM, bv + i * DDIM,
            q, k, v);

        attn_kernel<<<grid_attn, ATTN_THREADS, ATTN_SMEM>>>(q, k, v, ctx);

        add_ln_kernel<<<ln_grid, 256>>>(x, ctx, nullptr,
                                        g1 + i * DDIM, be1 + i * DDIM, xh, xl, nullptr);

        ff1_gemm_kernel<<<grid_ff1, 256>>>(xh, xl, W1h + of, W1l + of,
                                           b1 + i * FFDIM, hh, hl);
        ff2_gemm_kernel<<<grid_ff2, 256>>>(hh, hl, W2h + of, W2l + of,
                                           b2 + i * DDIM, ctx, p1);

        add_ln_kernel<<<ln_grid, 256>>>(x, ctx, p1,
                                        g2 + i * DDIM, be2 + i * DDIM, xh, xl,
                                        (i == LAYERS - 1) ? out : nullptr);
    }
}

// round 16
// speedup vs baseline: 2.0939x; 1.1158x over previous
#include <cuda_runtime.h>
#include <cuda_bf16.h>
#include <math.h>
#include <stdint.h>

// Problem constants
#define NB 4
#define LSEQ 256
#define MMEM 2
#define DDIM 768
#define HNUM 12
#define FFDIM 3072
#define LAYERS 4
#define TTOT 1032
#define KKEYS 258

typedef __nv_bfloat16 bf16;

// -------- scratch (device globals) --------
__device__ float g_x[TTOT * DDIM];
__device__ float g_q[TTOT * DDIM];
__device__ float g_k[TTOT * DDIM];
__device__ float g_v[TTOT * DDIM];
__device__ float g_ctx[TTOT * DDIM];
__device__ float g_p1[TTOT * DDIM];

__device__ bf16 g_xh[TTOT * DDIM];
__device__ bf16 g_xl[TTOT * DDIM];
__device__ bf16 g_hh[TTOT * FFDIM];
__device__ bf16 g_hl[TTOT * FFDIM];

// pre-split weights (bf16 hi/lo, original [K][N] row-major layout)
__device__ bf16 g_Wqh[LAYERS * DDIM * DDIM];
__device__ bf16 g_Wql[LAYERS * DDIM * DDIM];
__device__ bf16 g_Wkh[LAYERS * DDIM * DDIM];
__device__ bf16 g_Wkl[LAYERS * DDIM * DDIM];
__device__ bf16 g_Wvh[LAYERS * DDIM * DDIM];
__device__ bf16 g_Wvl[LAYERS * DDIM * DDIM];
__device__ bf16 g_W1h[LAYERS * DDIM * FFDIM];
__device__ bf16 g_W1l[LAYERS * DDIM * FFDIM];
__device__ bf16 g_W2h[LAYERS * DDIM * FFDIM];
__device__ bf16 g_W2l[LAYERS * DDIM * FFDIM];

__device__ float g_zero_bias[DDIM];   // zero-initialized

// ================= helpers =================
__device__ __forceinline__ uint32_t packbf(bf16 a, bf16 b) {
    __nv_bfloat162 t = __nv_bfloat162(a, b);
    return *reinterpret_cast<uint32_t*>(&t);
}
__device__ __forceinline__ void split1(float v, bf16& h, bf16& l) {
    h = __float2bfloat16(v);
    l = __float2bfloat16(v - __bfloat162float(h));
}
__device__ __forceinline__ void split4(float4 v, uint2& hi, uint2& lo) {
    bf16 h0, l0, h1, l1, h2, l2, h3, l3;
    split1(v.x, h0, l0); split1(v.y, h1, l1);
    split1(v.z, h2, l2); split1(v.w, h3, l3);
    hi.x = packbf(h0, h1); hi.y = packbf(h2, h3);
    lo.x = packbf(l0, l1); lo.y = packbf(l2, l3);
}
__device__ __forceinline__ void ldsm_x4(uint32_t* r, uint32_t addr) {
    asm volatile("ldmatrix.sync.aligned.m8n8.x4.shared.b16 {%0,%1,%2,%3}, [%4];\n"
        : "=r"(r[0]), "=r"(r[1]), "=r"(r[2]), "=r"(r[3]) : "r"(addr));
}
__device__ __forceinline__ void ldsm_x4_t(uint32_t* r, uint32_t addr) {
    asm volatile("ldmatrix.sync.aligned.m8n8.x4.trans.shared.b16 {%0,%1,%2,%3}, [%4];\n"
        : "=r"(r[0]), "=r"(r[1]), "=r"(r[2]), "=r"(r[3]) : "r"(addr));
}
__device__ __forceinline__ void mma_bf16(float* c, const uint32_t* a, const uint32_t* b) {
    asm volatile("mma.sync.aligned.m16n8k16.row.col.f32.bf16.bf16.f32 "
        "{%0,%1,%2,%3}, {%4,%5,%6,%7}, {%8,%9}, {%0,%1,%2,%3};\n"
        : "+f"(c[0]), "+f"(c[1]), "+f"(c[2]), "+f"(c[3])
        : "r"(a[0]), "r"(a[1]), "r"(a[2]), "r"(a[3]), "r"(b[0]), "r"(b[1]));
}
__device__ __forceinline__ void cpa16s(void* dst, const void* src, int sz) {
    uint32_t d = (uint32_t)__cvta_generic_to_shared(dst);
    asm volatile("cp.async.cg.shared.global [%0], [%1], 16, %2;\n"
        :: "r"(d), "l"(src), "r"(sz));
}
__device__ __forceinline__ void cp_commit() {
    asm volatile("cp.async.commit_group;\n");
}
template<int N>
__device__ __forceinline__ void cp_wait() {
    asm volatile("cp.async.wait_group %0;\n" :: "n"(N));
}

// smem XOR swizzles (conflict-free for ldmatrix, 16B-aligned for cp.async)
__device__ __forceinline__ int swzA(int row, int col) {   // 32 cols
    int chunk = (col >> 3) ^ ((row >> 1) & 3);
    return row * 32 + chunk * 8;
}
__device__ __forceinline__ int swzB(int row, int col) {   // 64 cols
    int chunk = (col >> 3) ^ (row & 7);
    return row * 64 + chunk * 8;
}

// ================= fused weight split (all 5 weights, one launch) =================
__global__ __launch_bounds__(256)
void convw_all_kernel(const float4* __restrict__ Wq, const float4* __restrict__ Wk,
                      const float4* __restrict__ Wv, const float4* __restrict__ W1,
                      const float4* __restrict__ W2,
                      bf16* __restrict__ Wqh, bf16* __restrict__ Wql,
                      bf16* __restrict__ Wkh, bf16* __restrict__ Wkl,
                      bf16* __restrict__ Wvh, bf16* __restrict__ Wvl,
                      bf16* __restrict__ W1h, bf16* __restrict__ W1l,
                      bf16* __restrict__ W2h, bf16* __restrict__ W2l,
                      int nqkv4, int nff4)
{
    const float4* src;
    bf16 *h, *l;
    int n4;
    switch (blockIdx.y) {
        case 0: src = Wq; h = Wqh; l = Wql; n4 = nqkv4; break;
        case 1: src = Wk; h = Wkh; l = Wkl; n4 = nqkv4; break;
        case 2: src = Wv; h = Wvh; l = Wvl; n4 = nqkv4; break;
        case 3: src = W1; h = W1h; l = W1l; n4 = nff4;  break;
        default: src = W2; h = W2h; l = W2l; n4 = nff4;  break;
    }
    int stride = gridDim.x * blockDim.x;
    for (int idx = blockIdx.x * blockDim.x + threadIdx.x; idx < n4; idx += stride) {
        float4 v = src[idx];
        uint2 hi, lo;
        split4(v, hi, lo);
        *(uint2*)&h[idx * 4] = hi;
        *(uint2*)&l[idx * 4] = lo;
    }
}

// ================= embedding =================
__global__ void embed_kernel(const int* __restrict__ ids,
                             const float* __restrict__ memory,
                             const float* __restrict__ emb,
                             const float* __restrict__ pos,
                             float* __restrict__ x,
                             bf16* __restrict__ xh, bf16* __restrict__ xl)
{
    int idx = blockIdx.x * blockDim.x + threadIdx.x;
    if (idx >= TTOT * DDIM) return;
    int t = idx / DDIM;
    int d = idx - t * DDIM;
    float val;
    if (t < NB * MMEM) {
        val = memory[idx] + pos[(t & 1) * DDIM + d];
    } else {
        int tt = t - NB * MMEM;
        int tok = ids[tt];
        val = emb[(size_t)tok * DDIM + d] + pos[(MMEM + (tt & (LSEQ - 1))) * DDIM + d];
    }
    x[idx] = val;
    bf16 h, l;
    split1(val, h, l);
    xh[idx] = h; xl[idx] = l;
}

// ================= pipelined bf16x3 GEMM (proven R7 config) =================
// BM=128, BN=64, BK=32; 256 threads = 8 warps (4m x 2n), warptile 32x32.

struct __align__(16) SmemGemm {
    bf16 Ah[2][128 * 32];
    bf16 Al[2][128 * 32];
    bf16 Bh[2][32 * 64];
    bf16 Bl[2][32 * 64];
};

template<int ACT>
__device__ __forceinline__ void gemm_core(
    const bf16* __restrict__ Agh, const bf16* __restrict__ Agl,
    const bf16* __restrict__ Bgh, const bf16* __restrict__ Bgl,
    const float* __restrict__ bias,
    float* __restrict__ C, bf16* __restrict__ Ch, bf16* __restrict__ Cl,
    int Mr, int K, int Nc, int row0, int col0, int kStart, int kLen)
{
    __shared__ SmemGemm s;

    int tid = threadIdx.x;
    int lane = tid & 31;
    int wid = tid >> 5;
    int wm = wid & 3;
    int wn = wid >> 2;
    int lrow = lane & 15;
    int lcol8 = (lane >> 4) * 8;

    float acc[2][4][4];
    #pragma unroll
    for (int im = 0; im < 2; im++)
        #pragma unroll
        for (int in = 0; in < 4; in++)
            #pragma unroll
            for (int r = 0; r < 4; r++) acc[im][in][r] = 0.f;

    int arow = tid >> 2;
    int acol = (tid & 3) * 8;
    int brow = tid >> 3;
    int bcol = (tid & 7) * 8;

    auto load_stage = [&](int st, int k0) {
        #pragma unroll
        for (int i = 0; i < 2; i++) {
            int row = arow + i * 64;
            int grow = row0 + row;
            int ok = (grow < Mr) ? 16 : 0;
            int gr = (grow < Mr) ? grow : 0;
            const bf16* sh = &Agh[(size_t)gr * K + kStart + k0 + acol];
            const bf16* sl = &Agl[(size_t)gr * K + kStart + k0 + acol];
            cpa16s(&s.Ah[st][swzA(row, acol)], sh, ok);
            cpa16s(&s.Al[st][swzA(row, acol)], sl, ok);
        }
        cpa16s(&s.Bh[st][swzB(brow, bcol)],
               &Bgh[(size_t)(kStart + k0 + brow) * Nc + col0 + bcol], 16);
        cpa16s(&s.Bl[st][swzB(brow, bcol)],
               &Bgl[(size_t)(kStart + k0 + brow) * Nc + col0 + bcol], 16);
        cp_commit();
    };

    int nit = kLen / 32;
    load_stage(0, 0);

    for (int iter = 0; iter < nit; iter++) {
        int st = iter & 1;
        if (iter + 1 < nit) {
            load_stage(st ^ 1, (iter + 1) * 32);
            cp_wait<1>();
        } else {
            cp_wait<0>();
        }
        __syncthreads();

        #pragma unroll
        for (int ks = 0; ks < 32; ks += 16) {
            uint32_t ah[2][4], al[2][4];
            #pragma unroll
            for (int im = 0; im < 2; im++) {
                int mrow = wm * 32 + im * 16 + lrow;
                int mcol = ks + lcol8;
                ldsm_x4(ah[im], (uint32_t)__cvta_generic_to_shared(&s.Ah[st][swzA(mrow, mcol)]));
                ldsm_x4(al[im], (uint32_t)__cvta_generic_to_shared(&s.Al[st][swzA(mrow, mcol)]));
            }
            uint32_t bh[4][2], bl[4][2];
            #pragma unroll
            for (int g = 0; g < 2; g++) {
                int br = ks + lrow;
                int bc = wn * 32 + g * 16 + lcol8;
                uint32_t t[4];
                ldsm_x4_t(t, (uint32_t)__cvta_generic_to_shared(&s.Bh[st][swzB(br, bc)]));
                bh[2*g][0] = t[0]; bh[2*g][1] = t[1]; bh[2*g+1][0] = t[2]; bh[2*g+1][1] = t[3];
                ldsm_x4_t(t, (uint32_t)__cvta_generic_to_shared(&s.Bl[st][swzB(br, bc)]));
                bl[2*g][0] = t[0]; bl[2*g][1] = t[1]; bl[2*g+1][0] = t[2]; bl[2*g+1][1] = t[3];
            }
            #pragma unroll
            for (int im = 0; im < 2; im++)
                #pragma unroll
                for (int in = 0; in < 4; in++) {
                    mma_bf16(acc[im][in], ah[im], bh[in]);
                    mma_bf16(acc[im][in], ah[im], bl[in]);
                    mma_bf16(acc[im][in], al[im], bh[in]);
                }
        }
        __syncthreads();
    }

    #pragma unroll
    for (int im = 0; im < 2; im++) {
        int rbase = row0 + wm * 32 + im * 16 + (lane >> 2);
        #pragma unroll
        for (int in = 0; in < 4; in++) {
            int cc = col0 + wn * 32 + in * 8 + (lane & 3) * 2;
            float bs0 = bias[cc], bs1 = bias[cc + 1];
            #pragma unroll
            for (int half = 0; half < 2; half++) {
                int r = rbase + half * 8;
                if (r >= Mr) continue;
                float v0 = acc[im][in][half * 2 + 0] + bs0;
                float v1 = acc[im][in][half * 2 + 1] + bs1;
                if (ACT == 1) {
                    v0 = 0.5f * v0 * (1.f + erff(v0 * 0.70710678118654752f));
                    v1 = 0.5f * v1 * (1.f + erff(v1 * 0.70710678118654752f));
                    bf16 h0, l0, h1, l1;
                    split1(v0, h0, l0); split1(v1, h1, l1);
                    *(uint32_t*)&Ch[(size_t)r * Nc + cc] = packbf(h0, h1);
                    *(uint32_t*)&Cl[(size_t)r * Nc + cc] = packbf(l0, l1);
                } else {
                    *(float2*)&C[(size_t)r * Nc + cc] = make_float2(v0, v1);
                }
            }
        }
    }
}

__global__ __launch_bounds__(256)
void qkv_gemm_kernel(const bf16* __restrict__ xh, const bf16* __restrict__ xl,
                     const bf16* __restrict__ Wqh, const bf16* __restrict__ Wql,
                     const bf16* __restrict__ Wkh, const bf16* __restrict__ Wkl,
                     const bf16* __restrict__ Wvh, const bf16* __restrict__ Wvl,
                     const float* __restrict__ bq, const float* __restrict__ bk,
                     const float* __restrict__ bv,
                     float* __restrict__ q, float* __restrict__ k, float* __restrict__ v)
{
    const bf16 *Wh, *Wl; const float* b; float* o;
    if (blockIdx.z == 0)      { Wh = Wqh; Wl = Wql; b = bq; o = q; }
    else if (blockIdx.z == 1) { Wh = Wkh; Wl = Wkl; b = bk; o = k; }
    else                      { Wh = Wvh; Wl = Wvl; b = bv; o = v; }
    gemm_core<0>(xh, xl, Wh, Wl, b, o, nullptr, nullptr,
                 TTOT, DDIM, DDIM, blockIdx.y * 128, blockIdx.x * 64, 0, DDIM);
}

__global__ __launch_bounds__(256)
void ff1_gemm_kernel(const bf16* __restrict__ xh, const bf16* __restrict__ xl,
                     const bf16* __restrict__ W1h, const bf16* __restrict__ W1l,
                     const float* __restrict__ b1,
                     bf16* __restrict__ hh, bf16* __restrict__ hl)
{
    gemm_core<1>(xh, xl, W1h, W1l, b1, nullptr, hh, hl,
                 TTOT, DDIM, FFDIM, blockIdx.y * 128, blockIdx.x * 64, 0, DDIM);
}

__global__ __launch_bounds__(256)
void ff2_gemm_kernel(const bf16* __restrict__ hh, const bf16* __restrict__ hl,
                     const bf16* __restrict__ W2h, const bf16* __restrict__ W2l,
                     const float* __restrict__ b2,
                     float* __restrict__ ctx, float* __restrict__ p1)
{
    int z = blockIdx.z;
    const float* b = (z == 0) ? b2 : g_zero_bias;
    float* o = (z == 0) ? ctx : p1;
    gemm_core<0>(hh, hl, W2h, W2l, b, o, nullptr, nullptr,
                 TTOT, FFDIM, DDIM, blockIdx.y * 128, blockIdx.x * 64,
                 z * (FFDIM / 2), FFDIM / 2);
}

// ================= attention =================
// grid (NB, HNUM, 3): 144 blocks. 352 threads = 4 key-groups x 88 slots
// (86 active query slots per group). Group g handles keys [g*KKEYS/4,(g+1)*KKEYS/4).
// No-max softmax partials (sum_e*V, sum_e) combine additively; groups 1-3
// park partials in the dead K/V smem region, group 0 merges.
#define QG3 86
#define ATTN_THREADS 352
#define ATTN_SMEM (2 * KKEYS * 64 * 4)

__global__ __launch_bounds__(ATTN_THREADS)
void attn_kernel(const float* __restrict__ q, const float* __restrict__ k,
                 const float* __restrict__ v, float* __restrict__ ctx)
{
    extern __shared__ float asm_[];
    float* Ks = asm_;
    float* Vs = asm_ + KKEYS * 64;

    int b = blockIdx.x;
    int h = blockIdx.y;
    int zg = blockIdx.z;
    int tid = threadIdx.x;

    for (int i = tid; i < KKEYS * 16; i += ATTN_THREADS) {
        int j = i >> 4, c = i & 15;
        int key = (j < MMEM) ? (2 * b + j) : (8 + b * LSEQ + (j - MMEM));
        size_t off = (size_t)key * DDIM + h * 64 + c * 4;
        ((float4*)Ks)[i] = *(const float4*)&k[off];
        ((float4*)Vs)[i] = *(const float4*)&v[off];
    }
    __syncthreads();

    int g = tid / 88;              // key-group 0..3
    int qt = tid - g * 88;         // query slot within group
    int qi = zg * QG3 + qt;        // query index 0..257
    bool active = (qt < QG3);

    float4 acc[16];
    float l = 0.f;
    size_t qoff = 0;

    if (active) {
        int t = (qi < MMEM) ? (2 * b + qi) : (8 + b * LSEQ + (qi - MMEM));
        qoff = (size_t)t * DDIM + h * 64;

        float4 qr[16];
        #pragma unroll
        for (int i = 0; i < 16; i++) {
            float4 qv = *(const float4*)&q[qoff + i * 4];
            qr[i] = make_float4(qv.x * 0.125f, qv.y * 0.125f, qv.z * 0.125f, qv.w * 0.125f);
        }
        #pragma unroll
        for (int i = 0; i < 16; i++) acc[i] = make_float4(0.f, 0.f, 0.f, 0.f);

        int j0 = (g * KKEYS) >> 2;         // 0,64,129,193
        int j1 = ((g + 1) * KKEYS) >> 2;   // 64,129,193,258
        for (int j = j0; j < j1; j++) {
            const float4* kr = (const float4*)(Ks + j * 64);
            float s0 = 0.f, s1 = 0.f, s2 = 0.f, s3 = 0.f;
            #pragma unroll
            for (int i = 0; i < 16; i += 4) {
                float4 k0 = kr[i], k1 = kr[i+1], k2 = kr[i+2], k3 = kr[i+3];
                s0 += qr[i].x * k0.x + qr[i].y * k0.y + qr[i].z * k0.z + qr[i].w * k0.w;
                s1 += qr[i+1].x * k1.x + qr[i+1].y * k1.y + qr[i+1].z * k1.z + qr[i+1].w * k1.w;
                s2 += qr[i+2].x * k2.x + qr[i+2].y * k2.y + qr[i+2].z * k2.z + qr[i+2].w * k2.w;
                s3 += qr[i+3].x * k3.x + qr[i+3].y * k3.y + qr[i+3].z * k3.z + qr[i+3].w * k3.w;
            }
            float p = __expf((s0 + s1) + (s2 + s3));
            l += p;
            const float4* vr = (const float4*)(Vs + j * 64);
            #pragma unroll
            for (int i = 0; i < 16; i++) {
                float4 vv = vr[i];
                acc[i].x += p * vv.x; acc[i].y += p * vv.y;
                acc[i].z += p * vv.z; acc[i].w += p * vv.w;
            }
        }
    }

    __syncthreads();   // all K/V reads complete; smem reusable

    // partial buffer: groups 1..3 park (acc, l) = 65 floats (stride 68)
    float* P = asm_;
    if (active && g > 0) {
        float* p = P + ((g - 1) * QG3 + qt) * 68;
        #pragma unroll
        for (int i = 0; i < 16; i++) {
            p[i * 4 + 0] = acc[i].x; p[i * 4 + 1] = acc[i].y;
            p[i * 4 + 2] = acc[i].z; p[i * 4 + 3] = acc[i].w;
        }
        p[64] = l;
    }
    __syncthreads();

    if (active && g == 0) {
        #pragma unroll
        for (int gg = 0; gg < 3; gg++) {
            const float* p = P + (gg * QG3 + qt) * 68;
            #pragma unroll
            for (int i = 0; i < 16; i++) {
                acc[i].x += p[i * 4 + 0]; acc[i].y += p[i * 4 + 1];
                acc[i].z += p[i * 4 + 2]; acc[i].w += p[i * 4 + 3];
            }
            l += p[64];
        }
        float inv = 1.f / l;
        #pragma unroll
        for (int i = 0; i < 16; i++) {
            float4 o = make_float4(acc[i].x * inv, acc[i].y * inv,
                                   acc[i].z * inv, acc[i].w * inv);
            *(float4*)&ctx[qoff + i * 4] = o;
        }
    }
}

// ================= residual add + LN (warp per token) =================
__global__ __launch_bounds__(256)
void add_ln_kernel(float* __restrict__ x, const float* __restrict__ r,
                   const float* __restrict__ r2,
                   const float* __restrict__ g, const float* __restrict__ b,
                   bf16* __restrict__ xh, bf16* __restrict__ xl,
                   float* __restrict__ out)
{
    int wid = threadIdx.x >> 5;
    int lane = threadIdx.x & 31;
    int t = blockIdx.x * 8 + wid;
    if (t >= TTOT) return;

    const float4* xp = (const float4*)(x + (size_t)t * DDIM);
    const float4* rp = (const float4*)(r + (size_t)t * DDIM);
    const float4* r2p = r2 ? (const float4*)(r2 + (size_t)t * DDIM) : nullptr;
    const float4* gp = (const float4*)g;
    const float4* bp = (const float4*)b;

    float4 v[6];
    float sum = 0.f;
    #pragma unroll
    for (int i = 0; i < 6; i++) {
        int idx = lane + i * 32;
        float4 a = xp[idx], c = rp[idx];
        v[i] = make_float4(a.x + c.x, a.y + c.y, a.z + c.z, a.w + c.w);
        if (r2p) {
            float4 e = r2p[idx];
            v[i].x += e.x; v[i].y += e.y; v[i].z += e.z; v[i].w += e.w;
        }
        sum += v[i].x + v[i].y + v[i].z + v[i].w;
    }
    #pragma unroll
    for (int o = 16; o > 0; o >>= 1) sum += __shfl_xor_sync(0xffffffffu, sum, o);
    float mu = sum * (1.f / DDIM);

    float var = 0.f;
    #pragma unroll
    for (int i = 0; i < 6; i++) {
        float dx = v[i].x - mu, dy = v[i].y - mu, dz = v[i].z - mu, dw = v[i].w - mu;
        var += dx * dx + dy * dy + dz * dz + dw * dw;
    }
    #pragma unroll
    for (int o = 16; o > 0; o >>= 1) var += __shfl_xor_sync(0xffffffffu, var, o);
    float rstd = rsqrtf(var * (1.f / DDIM) + 1e-5f);

    float4* xo = (float4*)(x + (size_t)t * DDIM);
    float4* oo = (out && t >= NB * MMEM)
               ? (float4*)(out + (size_t)(t - NB * MMEM) * DDIM) : nullptr;
    #pragma unroll
    for (int i = 0; i < 6; i++) {
        int idx = lane + i * 32;
        float4 gg = gp[idx], bb = bp[idx];
        float4 o;
        o.x = (v[i].x - mu) * rstd * gg.x + bb.x;
        o.y = (v[i].y - mu) * rstd * gg.y + bb.y;
        o.z = (v[i].z - mu) * rstd * gg.z + bb.z;
        o.w = (v[i].w - mu) * rstd * gg.w + bb.w;
        xo[idx] = o;
        if (oo) oo[idx] = o;
        uint2 hi, lo;
        split4(o, hi, lo);
        *(uint2*)&xh[(size_t)t * DDIM + idx * 4] = hi;
        *(uint2*)&xl[(size_t)t * DDIM + idx * 4] = lo;
    }
}

extern "C" void kernel_launch(void* const* d_in, const int* in_sizes, int n_in,
                              void* d_out, int out_size)
{
    const int*   ids    = (const int*)  d_in[0];
    const float* memory = (const float*)d_in[1];
    const float* emb    = (const float*)d_in[2];
    const float* pos    = (const float*)d_in[3];
    const float* Wq     = (const float*)d_in[4];
    const float* bq     = (const float*)d_in[5];
    const float* Wk     = (const float*)d_in[6];
    const float* bk     = (const float*)d_in[7];
    const float* Wv     = (const float*)d_in[8];
    const float* bv     = (const float*)d_in[9];
    const float* W1     = (const float*)d_in[10];
    const float* b1     = (const float*)d_in[11];
    const float* W2     = (const float*)d_in[12];
    const float* b2     = (const float*)d_in[13];
    const float* g1     = (const float*)d_in[14];
    const float* be1    = (const float*)d_in[15];
    const float* g2     = (const float*)d_in[16];
    const float* be2    = (const float*)d_in[17];
    float* out = (float*)d_out;

    float *x, *q, *k, *v, *ctx, *p1;
    bf16 *xh, *xl, *hh, *hl;
    bf16 *Wqh, *Wql, *Wkh, *Wkl, *Wvh, *Wvl, *W1h, *W1l, *W2h, *W2l;
    cudaGetSymbolAddress((void**)&x,   g_x);
    cudaGetSymbolAddress((void**)&q,   g_q);
    cudaGetSymbolAddress((void**)&k,   g_k);
    cudaGetSymbolAddress((void**)&v,   g_v);
    cudaGetSymbolAddress((void**)&ctx, g_ctx);
    cudaGetSymbolAddress((void**)&p1,  g_p1);
    cudaGetSymbolAddress((void**)&xh,  g_xh);
    cudaGetSymbolAddress((void**)&xl,  g_xl);
    cudaGetSymbolAddress((void**)&hh,  g_hh);
    cudaGetSymbolAddress((void**)&hl,  g_hl);
    cudaGetSymbolAddress((void**)&Wqh, g_Wqh);
    cudaGetSymbolAddress((void**)&Wql, g_Wql);
    cudaGetSymbolAddress((void**)&Wkh, g_Wkh);
    cudaGetSymbolAddress((void**)&Wkl, g_Wkl);
    cudaGetSymbolAddress((void**)&Wvh, g_Wvh);
    cudaGetSymbolAddress((void**)&Wvl, g_Wvl);
    cudaGetSymbolAddress((void**)&W1h, g_W1h);
    cudaGetSymbolAddress((void**)&W1l, g_W1l);
    cudaGetSymbolAddress((void**)&W2h, g_W2h);
    cudaGetSymbolAddress((void**)&W2l, g_W2l);

    cudaFuncSetAttribute(attn_kernel, cudaFuncAttributeMaxDynamicSharedMemorySize, ATTN_SMEM);

    int nqkv4 = LAYERS * DDIM * DDIM / 4;       // 589824
    int nff4  = LAYERS * DDIM * FFDIM / 4;      // 2359296

    embed_kernel<<<(TTOT * DDIM + 255) / 256, 256>>>(ids, memory, emb, pos, x, xh, xl);
    convw_all_kernel<<<dim3(2304, 5), 256>>>(
        (const float4*)Wq, (const float4*)Wk, (const float4*)Wv,
        (const float4*)W1, (const float4*)W2,
        Wqh, Wql, Wkh, Wkl, Wvh, Wvl, W1h, W1l, W2h, W2l,
        nqkv4, nff4);

    const int MB = (TTOT + 127) / 128;          // 9
    dim3 grid_qkv(DDIM / 64, MB, 3);            // (12, 9, 3)
    dim3 grid_ff1(FFDIM / 64, MB);              // (48, 9)
    dim3 grid_ff2(DDIM / 64, MB, 2);            // (12, 9, 2) split-K
    dim3 grid_attn(NB, HNUM, 3);                // (4, 12, 3) = 144 blocks
    int ln_grid = (TTOT + 7) / 8;               // 129

    for (int i = 0; i < LAYERS; i++) {
        size_t od = (size_t)i * DDIM * DDIM;
        size_t of = (size_t)i * DDIM * FFDIM;
        qkv_gemm_kernel<<<grid_qkv, 256>>>(
            xh, xl,
            Wqh + od, Wql + od, Wkh + od, Wkl + od, Wvh + od, Wvl + od,
            bq + i * DDIM, bk + i * DDIM, bv + i * DDIM,
            q, k, v);

        attn_kernel<<<grid_attn, ATTN_THREADS, ATTN_SMEM>>>(q, k, v, ctx);

        add_ln_kernel<<<ln_grid, 256>>>(x, ctx, nullptr,
                                        g1 + i * DDIM, be1 + i * DDIM, xh, xl, nullptr);

        ff1_gemm_kernel<<<grid_ff1, 256>>>(xh, xl, W1h + of, W1l + of,
                                           b1 + i * FFDIM, hh, hl);
        ff2_gemm_kernel<<<grid_ff2, 256>>>(hh, hl, W2h + of, W2l + of,
                                           b2 + i * DDIM, ctx, p1);

        add_ln_kernel<<<ln_grid, 256>>>(x, ctx, p1,
                                        g2 + i * DDIM, be2 + i * DDIM, xh, xl,
                                        (i == LAYERS - 1) ? out : nullptr);
    }
}